// round 1
// baseline (speedup 1.0000x reference)
#include <cuda_runtime.h>
#include <math.h>

// Problem constants
constexpr int Bb    = 2;
constexpr int Ss    = 1024;
constexpr int Dd    = 1024;
constexpr int Hh    = 8;
constexpr int HD    = 128;
constexpr int DEPTH = 8;
constexpr int FF    = 4096;
constexpr int BS    = Bb * Ss;      // 2048
constexpr int RSPLIT = 32;

// Scratch (device globals: allocation-free)
__device__ float g_x [BS * Dd];
__device__ float g_xn[BS * Dd];
__device__ float g_q [BS * Dd];
__device__ float g_kv[BS * 2 * Dd];
__device__ float g_attn[(size_t)Bb * Hh * Ss * Ss];   // 64 MB
__device__ float g_y [BS * Dd];
__device__ float g_ff[(size_t)BS * FF];               // 32 MB
__device__ float g_part[RSPLIT * Bb * Ss];

// ---------------------------------------------------------------- GEMM
// C[M,N] = epilogue(alpha * A[M,K] @ B[K,N])
// TRANSB: B stored [N,K] row-major (ldb = row stride), i.e. C = A @ B^T
// EPI: 0 = store, 1 = C += acc + bias[col], 2 = store gelu(acc), 3 = C += acc
#define BM 128
#define BN 64
#define BK 16
#define TM 8
#define TN 4

template<int EPI, bool TRANSB>
__global__ __launch_bounds__(256) void gemm_k(
    const float* __restrict__ A, const float* __restrict__ Bg,
    float* __restrict__ C, const float* __restrict__ bias,
    int K, int lda, int ldb, int ldc,
    long long sAo, long long sAi, long long sBo, long long sBi,
    long long sCo, long long sCi, int zdiv,
    float alpha, int causal)
{
    const int bm = blockIdx.y * BM;
    const int bn = blockIdx.x * BN;
    if (causal && bn >= bm + BM) return;   // tile fully above causal diagonal

    const int z  = blockIdx.z;
    const int zo = z / zdiv;
    const int zi = z - zo * zdiv;
    A  += zo * sAo + zi * sAi;
    Bg += zo * sBo + zi * sBi;
    C  += zo * sCo + zi * sCi;

    __shared__ float As[BM][BK];
    __shared__ float Bs[BK][BN];

    const int tid = threadIdx.x;
    const int tx  = tid & 15;       // N dir
    const int ty  = tid >> 4;       // M dir

    float acc[TM][TN];
    #pragma unroll
    for (int i = 0; i < TM; i++)
        #pragma unroll
        for (int j = 0; j < TN; j++) acc[i][j] = 0.f;

    const int ar0 = tid >> 2;       // 0..63
    const int ac4 = tid & 3;        // 0..3 (float4 within 16)

    for (int k0 = 0; k0 < K; k0 += BK) {
        // Load A tile (BM x BK), 2 float4 per thread
        #pragma unroll
        for (int h = 0; h < 2; h++) {
            int r = ar0 + h * 64;
            float4 v = *(const float4*)&A[(long long)(bm + r) * lda + k0 + ac4 * 4];
            *(float4*)&As[r][ac4 * 4] = v;
        }
        // Load B tile (BK x BN)
        if (!TRANSB) {
            int br  = tid >> 4;     // 0..15
            int bc4 = tid & 15;     // 0..15
            float4 v = *(const float4*)&Bg[(long long)(k0 + br) * ldb + bn + bc4 * 4];
            *(float4*)&Bs[br][bc4 * 4] = v;
        } else {
            int nr  = tid >> 2;     // 0..63
            int kc4 = tid & 3;
            float4 v = *(const float4*)&Bg[(long long)(bn + nr) * ldb + k0 + kc4 * 4];
            Bs[kc4 * 4 + 0][nr] = v.x;
            Bs[kc4 * 4 + 1][nr] = v.y;
            Bs[kc4 * 4 + 2][nr] = v.z;
            Bs[kc4 * 4 + 3][nr] = v.w;
        }
        __syncthreads();

        #pragma unroll
        for (int k = 0; k < BK; k++) {
            float a[TM];
            #pragma unroll
            for (int i = 0; i < TM; i++) a[i] = As[ty * TM + i][k];
            float4 b4 = *(const float4*)&Bs[k][tx * TN];
            float bv[TN] = {b4.x, b4.y, b4.z, b4.w};
            #pragma unroll
            for (int i = 0; i < TM; i++)
                #pragma unroll
                for (int j = 0; j < TN; j++)
                    acc[i][j] = fmaf(a[i], bv[j], acc[i][j]);
        }
        __syncthreads();
    }

    // Epilogue (float4)
    #pragma unroll
    for (int i = 0; i < TM; i++) {
        long long r = bm + ty * TM + i;
        float* cp = &C[r * (long long)ldc + bn + tx * TN];
        float4 v = make_float4(acc[i][0] * alpha, acc[i][1] * alpha,
                               acc[i][2] * alpha, acc[i][3] * alpha);
        if (EPI == 0) {
            *(float4*)cp = v;
        } else if (EPI == 1) {
            float4 o  = *(const float4*)cp;
            float4 bb = *(const float4*)&bias[bn + tx * TN];
            o.x += v.x + bb.x; o.y += v.y + bb.y;
            o.z += v.z + bb.z; o.w += v.w + bb.w;
            *(float4*)cp = o;
        } else if (EPI == 2) {
            const float c = 0.70710678118654752f;
            v.x = 0.5f * v.x * erfcf(-v.x * c);
            v.y = 0.5f * v.y * erfcf(-v.y * c);
            v.z = 0.5f * v.z * erfcf(-v.z * c);
            v.w = 0.5f * v.w * erfcf(-v.w * c);
            *(float4*)cp = v;
        } else {
            float4 o = *(const float4*)cp;
            o.x += v.x; o.y += v.y; o.z += v.z; o.w += v.w;
            *(float4*)cp = o;
        }
    }
}

// ---------------------------------------------------------------- LayerNorm
__global__ __launch_bounds__(256) void ln_k(
    const float* __restrict__ x, const float* __restrict__ g,
    const float* __restrict__ b, float* __restrict__ out)
{
    __shared__ float sm0[8], sm1[8];
    const int row = blockIdx.x, tid = threadIdx.x;
    float4 v = ((const float4*)(x + (long long)row * Dd))[tid];
    float s  = v.x + v.y + v.z + v.w;
    float s2 = v.x * v.x + v.y * v.y + v.z * v.z + v.w * v.w;
    #pragma unroll
    for (int o = 16; o > 0; o >>= 1) {
        s  += __shfl_xor_sync(0xffffffffu, s,  o);
        s2 += __shfl_xor_sync(0xffffffffu, s2, o);
    }
    if ((tid & 31) == 0) { sm0[tid >> 5] = s; sm1[tid >> 5] = s2; }
    __syncthreads();
    if (tid < 32) {
        s  = (tid < 8) ? sm0[tid] : 0.f;
        s2 = (tid < 8) ? sm1[tid] : 0.f;
        #pragma unroll
        for (int o = 4; o > 0; o >>= 1) {
            s  += __shfl_xor_sync(0xffffffffu, s,  o);
            s2 += __shfl_xor_sync(0xffffffffu, s2, o);
        }
        if (tid == 0) { sm0[0] = s; sm1[0] = s2; }
    }
    __syncthreads();
    const float mean = sm0[0] * (1.f / Dd);
    const float var  = sm1[0] * (1.f / Dd) - mean * mean;
    const float rstd = rsqrtf(var + 1e-5f);
    float4 gg = ((const float4*)g)[tid];
    float4 bb = ((const float4*)b)[tid];
    float4 o;
    o.x = (v.x - mean) * rstd * gg.x + bb.x;
    o.y = (v.y - mean) * rstd * gg.y + bb.y;
    o.z = (v.z - mean) * rstd * gg.z + bb.z;
    o.w = (v.w - mean) * rstd * gg.w + bb.w;
    ((float4*)(out + (long long)row * Dd))[tid] = o;
}

// ---------------------------------------------------------------- Softmax (causal row)
__global__ __launch_bounds__(256) void softmax_k(float* __restrict__ attn)
{
    __shared__ float sm[8];
    const int row = blockIdx.x;
    const int q   = row & (Ss - 1);
    float* p = attn + (long long)row * Ss;
    const int tid = threadIdx.x;
    const int k0  = tid * 4;
    float4 v = ((const float4*)p)[tid];

    float m = -1e30f;
    if (k0 + 0 <= q) m = fmaxf(m, v.x);
    if (k0 + 1 <= q) m = fmaxf(m, v.y);
    if (k0 + 2 <= q) m = fmaxf(m, v.z);
    if (k0 + 3 <= q) m = fmaxf(m, v.w);
    #pragma unroll
    for (int o = 16; o > 0; o >>= 1) m = fmaxf(m, __shfl_xor_sync(0xffffffffu, m, o));
    if ((tid & 31) == 0) sm[tid >> 5] = m;
    __syncthreads();
    if (tid < 32) {
        float t = (tid < 8) ? sm[tid] : -1e30f;
        #pragma unroll
        for (int o = 4; o > 0; o >>= 1) t = fmaxf(t, __shfl_xor_sync(0xffffffffu, t, o));
        if (tid == 0) sm[0] = t;
    }
    __syncthreads();
    m = sm[0];
    __syncthreads();

    float4 e;
    e.x = (k0 + 0 <= q) ? __expf(v.x - m) : 0.f;
    e.y = (k0 + 1 <= q) ? __expf(v.y - m) : 0.f;
    e.z = (k0 + 2 <= q) ? __expf(v.z - m) : 0.f;
    e.w = (k0 + 3 <= q) ? __expf(v.w - m) : 0.f;
    float s = e.x + e.y + e.z + e.w;
    #pragma unroll
    for (int o = 16; o > 0; o >>= 1) s += __shfl_xor_sync(0xffffffffu, s, o);
    if ((tid & 31) == 0) sm[tid >> 5] = s;
    __syncthreads();
    if (tid < 32) {
        float t = (tid < 8) ? sm[tid] : 0.f;
        #pragma unroll
        for (int o = 4; o > 0; o >>= 1) t += __shfl_xor_sync(0xffffffffu, t, o);
        if (tid == 0) sm[0] = t;
    }
    __syncthreads();
    const float inv = 1.f / sm[0];
    e.x *= inv; e.y *= inv; e.z *= inv; e.w *= inv;
    ((float4*)p)[tid] = e;
}

// ---------------------------------------------------------------- Column sums (deterministic 2-stage)
__global__ __launch_bounds__(256) void colsum_part_k(
    const float* __restrict__ attn, float* __restrict__ part)
{
    const int k  = blockIdx.x * 256 + threadIdx.x;   // 0..1023
    const int b  = blockIdx.y;
    const int rs = blockIdx.z;
    const int RC = Hh * Ss / RSPLIT;                 // 256 rows per split
    const float* base = attn + (long long)b * Hh * Ss * Ss
                             + (long long)rs * RC * Ss + k;
    float s = 0.f;
    #pragma unroll 8
    for (int r = 0; r < RC; r++) s += base[(long long)r * Ss];
    part[(rs * Bb + b) * Ss + k] = s;
}

__global__ __launch_bounds__(256) void colsum_fin_k(
    const float* __restrict__ part, float* __restrict__ amap)
{
    const int i = blockIdx.x * 256 + threadIdx.x;    // 0..2047 (b*S+k)
    float s = 0.f;
    #pragma unroll
    for (int rs = 0; rs < RSPLIT; rs++) s += part[rs * Bb * Ss + i];
    amap[i] += s;
}

// ---------------------------------------------------------------- misc
__global__ __launch_bounds__(256) void save_ctx_k(
    const float* __restrict__ x, float4* __restrict__ st, int layer)
{
    const int i  = blockIdx.x * 256 + threadIdx.x;   // over BS*D/4
    const int d4 = i & 255;
    const int bs = i >> 8;
    st[((long long)bs * DEPTH + layer) * 256 + d4] = ((const float4*)x)[i];
}

__global__ void zero_k(float* p, int n)
{
    int i = blockIdx.x * 256 + threadIdx.x;
    if (i < n) p[i] = 0.f;
}

// ---------------------------------------------------------------- launcher
extern "C" void kernel_launch(void* const* d_in, const int* in_sizes, int n_in,
                              void* d_out, int out_size)
{
    const float* token = (const float*)d_in[0];
    const float* Wq    = (const float*)d_in[1];
    const float* Wkv   = (const float*)d_in[2];
    const float* Wo    = (const float*)d_in[3];
    const float* b_o   = (const float*)d_in[4];
    const float* g1    = (const float*)d_in[5];
    const float* b1    = (const float*)d_in[6];
    const float* g3    = (const float*)d_in[7];
    const float* b3    = (const float*)d_in[8];
    const float* W1    = (const float*)d_in[9];
    const float* W2    = (const float*)d_in[10];
    const float* gout  = (const float*)d_in[11];
    const float* bout  = (const float*)d_in[12];
    float* out = (float*)d_out;

    float *x, *xn, *q, *kv, *attn, *y, *ff, *part;
    cudaGetSymbolAddress((void**)&x,    g_x);
    cudaGetSymbolAddress((void**)&xn,   g_xn);
    cudaGetSymbolAddress((void**)&q,    g_q);
    cudaGetSymbolAddress((void**)&kv,   g_kv);
    cudaGetSymbolAddress((void**)&attn, g_attn);
    cudaGetSymbolAddress((void**)&y,    g_y);
    cudaGetSymbolAddress((void**)&ff,   g_ff);
    cudaGetSymbolAddress((void**)&part, g_part);

    float* out_state = out + (size_t)BS * Dd;
    float* amap      = out_state + (size_t)BS * DEPTH * Dd;

    cudaMemcpyAsync(x, token, sizeof(float) * BS * Dd, cudaMemcpyDeviceToDevice, 0);
    zero_k<<<(BS + 255) / 256, 256>>>(amap, BS);

    const float scale = rsqrtf((float)HD);

    for (int l = 0; l < DEPTH; l++) {
        // context snapshot
        save_ctx_k<<<BS * Dd / 4 / 256, 256>>>(x, (float4*)out_state, l);
        // LN1
        ln_k<<<BS, 256>>>(x, g1 + l * Dd, b1 + l * Dd, xn);
        // Q = xn @ Wq
        gemm_k<0, false><<<dim3(Dd / BN, BS / BM, 1), 256>>>(
            xn, Wq + (size_t)l * Dd * Dd, q, nullptr,
            Dd, Dd, Dd, Dd, 0, 0, 0, 0, 0, 0, 1, 1.f, 0);
        // KV = xn @ Wkv
        gemm_k<0, false><<<dim3(2 * Dd / BN, BS / BM, 1), 256>>>(
            xn, Wkv + (size_t)l * Dd * 2 * Dd, kv, nullptr,
            Dd, Dd, 2 * Dd, 2 * Dd, 0, 0, 0, 0, 0, 0, 1, 1.f, 0);
        // scores = scale * Q @ K^T  (batched over b,h; causal tile-skip)
        gemm_k<0, true><<<dim3(Ss / BN, Ss / BM, Bb * Hh), 256>>>(
            q, kv, attn, nullptr,
            HD, Dd, 2 * Dd, Ss,
            (long long)Ss * Dd, HD,
            (long long)Ss * 2 * Dd, HD,
            (long long)Hh * Ss * Ss, (long long)Ss * Ss,
            Hh, scale, 1);
        // softmax rows (mask + normalize + zero upper triangle)
        softmax_k<<<Bb * Hh * Ss, 256>>>(attn);
        // attention-map column sums
        colsum_part_k<<<dim3(Ss / 256, Bb, RSPLIT), 256>>>(attn, part);
        colsum_fin_k<<<Bb * Ss / 256, 256>>>(part, amap);
        // y = attn @ V
        gemm_k<0, false><<<dim3(HD / BN, Ss / BM, Bb * Hh), 256>>>(
            attn, kv + Dd, y, nullptr,
            Ss, Ss, 2 * Dd, Dd,
            (long long)Hh * Ss * Ss, (long long)Ss * Ss,
            (long long)Ss * 2 * Dd, HD,
            (long long)Ss * Dd, HD,
            Hh, 1.f, 0);
        // x += y @ Wo + b_o
        gemm_k<1, false><<<dim3(Dd / BN, BS / BM, 1), 256>>>(
            y, Wo + (size_t)l * Dd * Dd, x, b_o + l * Dd,
            Dd, Dd, Dd, Dd, 0, 0, 0, 0, 0, 0, 1, 1.f, 0);
        // LN2
        ln_k<<<BS, 256>>>(x, g3 + l * Dd, b3 + l * Dd, xn);
        // ff = gelu(xn @ W1)
        gemm_k<2, false><<<dim3(FF / BN, BS / BM, 1), 256>>>(
            xn, W1 + (size_t)l * Dd * FF, ff, nullptr,
            Dd, Dd, FF, FF, 0, 0, 0, 0, 0, 0, 1, 1.f, 0);
        // x += ff @ W2
        gemm_k<3, false><<<dim3(Dd / BN, BS / BM, 1), 256>>>(
            ff, W2 + (size_t)l * FF * Dd, x, nullptr,
            FF, FF, Dd, Dd, 0, 0, 0, 0, 0, 0, 1, 1.f, 0);
    }
    // final LN -> x_out
    ln_k<<<BS, 256>>>(x, gout, bout, out);
}

// round 2
// speedup vs baseline: 2.2095x; 2.2095x over previous
#include <cuda_runtime.h>
#include <math.h>

// Problem constants
constexpr int Bb    = 2;
constexpr int Ss    = 1024;
constexpr int Dd    = 1024;
constexpr int Hh    = 8;
constexpr int HD    = 128;
constexpr int DEPTH = 8;
constexpr int FF    = 4096;
constexpr int BS    = Bb * Ss;      // 2048
constexpr int RSPLIT = 32;

// Scratch (device globals: allocation-free)
__device__ float g_x [BS * Dd];
__device__ float g_xn[BS * Dd];
__device__ float g_q [BS * Dd];
__device__ float g_kv[BS * 2 * Dd];
__device__ float g_attn[(size_t)Bb * Hh * Ss * Ss];   // 64 MB
__device__ float g_y [BS * Dd];
__device__ float g_ff[(size_t)BS * FF];               // 32 MB
__device__ float g_part[RSPLIT * Bb * Ss];

// ---------------------------------------------------------------- tf32 helpers
__device__ __forceinline__ unsigned f2tf32(float x) {
    unsigned r;
    asm("cvt.rna.tf32.f32 %0, %1;" : "=r"(r) : "f"(x));
    return r;
}
__device__ __forceinline__ float tf32f(float x) {
    return __uint_as_float(f2tf32(x));
}

__device__ __forceinline__ void mma_tf32(float* c, const unsigned* a, const unsigned* b) {
    asm volatile(
        "mma.sync.aligned.m16n8k8.row.col.f32.tf32.tf32.f32 "
        "{%0,%1,%2,%3}, {%4,%5,%6,%7}, {%8,%9}, {%0,%1,%2,%3};"
        : "+f"(c[0]), "+f"(c[1]), "+f"(c[2]), "+f"(c[3])
        : "r"(a[0]), "r"(a[1]), "r"(a[2]), "r"(a[3]), "r"(b[0]), "r"(b[1]));
}

// ---------------------------------------------------------------- tensor-core GEMM
// C[M,N] = epilogue(alpha * A[M,K] @ B[K,N])
// TRANSB: B stored [N,K] row-major, i.e. C = A @ B^T
// EPI: 0 = store, 1 = C += acc + bias[col], 2 = store gelu(acc), 3 = C += acc
#define BM 128
#define BN 128
#define BK 16
#define ALEN 20     // As row length  (conflict-free fragment loads)
#define BLEN 132    // Bs row length  (<=2-way fragment loads)

template<int EPI, bool TRANSB>
__global__ __launch_bounds__(256) void gemm_tc(
    const float* __restrict__ A, const float* __restrict__ Bg,
    float* __restrict__ C, const float* __restrict__ bias,
    int K, int lda, int ldb, int ldc,
    long long sAo, long long sAi, long long sBo, long long sBi,
    long long sCo, long long sCi, int zdiv,
    float alpha, int causal)
{
    const int bm = blockIdx.y * BM;
    const int bn = blockIdx.x * BN;
    if (causal && bn >= bm + BM) return;   // fully above causal diagonal

    const int z  = blockIdx.z;
    const int zo = z / zdiv;
    const int zi = z - zo * zdiv;
    A  += zo * sAo + zi * sAi;
    Bg += zo * sBo + zi * sBi;
    C  += zo * sCo + zi * sCi;

    __shared__ float As[2][BM * ALEN];     // [m][k]
    __shared__ float Bs[2][BK * BLEN];     // [k][n]

    const int tid  = threadIdx.x;
    const int lane = tid & 31;
    const int warp = tid >> 5;
    const int wm   = (warp & 1) * 64;      // warp tile 64(M) x 32(N)
    const int wn   = (warp >> 1) * 32;
    const int g    = lane >> 2;            // 0..7
    const int t    = lane & 3;             // 0..3

    float acc[4][4][4];
    #pragma unroll
    for (int i = 0; i < 4; i++)
        #pragma unroll
        for (int j = 0; j < 4; j++)
            #pragma unroll
            for (int r = 0; r < 4; r++) acc[i][j][r] = 0.f;

    // A load mapping: 2 float4 per thread
    const int arow = tid >> 2;             // 0..63  (+64 for second)
    const int ac4  = (tid & 3) * 4;        // k offset
    // B load mapping (!TRANSB): rows of B tile
    const int bkr  = tid >> 5;             // 0..7  (+8 for second)
    const int bnc  = (tid & 31) * 4;       // n offset
    // B load mapping (TRANSB): rows are n
    const int tnr  = tid >> 2;             // 0..63 (+64)
    const int tkc  = (tid & 3) * 4;        // k offset

    float4 ra0, ra1, rb0, rb1;

    auto loadG = [&](int k0) {
        ra0 = *(const float4*)&A[(long long)(bm + arow) * lda + k0 + ac4];
        ra1 = *(const float4*)&A[(long long)(bm + arow + 64) * lda + k0 + ac4];
        if (!TRANSB) {
            rb0 = *(const float4*)&Bg[(long long)(k0 + bkr) * ldb + bn + bnc];
            rb1 = *(const float4*)&Bg[(long long)(k0 + bkr + 8) * ldb + bn + bnc];
        } else {
            rb0 = *(const float4*)&Bg[(long long)(bn + tnr) * ldb + k0 + tkc];
            rb1 = *(const float4*)&Bg[(long long)(bn + tnr + 64) * ldb + k0 + tkc];
        }
    };
    auto storeS = [&](int p) {
        float* a0 = &As[p][arow * ALEN + ac4];
        a0[0] = tf32f(ra0.x); a0[1] = tf32f(ra0.y); a0[2] = tf32f(ra0.z); a0[3] = tf32f(ra0.w);
        float* a1 = &As[p][(arow + 64) * ALEN + ac4];
        a1[0] = tf32f(ra1.x); a1[1] = tf32f(ra1.y); a1[2] = tf32f(ra1.z); a1[3] = tf32f(ra1.w);
        if (!TRANSB) {
            float* s0 = &Bs[p][bkr * BLEN + bnc];
            s0[0] = tf32f(rb0.x); s0[1] = tf32f(rb0.y); s0[2] = tf32f(rb0.z); s0[3] = tf32f(rb0.w);
            float* s1 = &Bs[p][(bkr + 8) * BLEN + bnc];
            s1[0] = tf32f(rb1.x); s1[1] = tf32f(rb1.y); s1[2] = tf32f(rb1.z); s1[3] = tf32f(rb1.w);
        } else {
            Bs[p][(tkc + 0) * BLEN + tnr] = tf32f(rb0.x);
            Bs[p][(tkc + 1) * BLEN + tnr] = tf32f(rb0.y);
            Bs[p][(tkc + 2) * BLEN + tnr] = tf32f(rb0.z);
            Bs[p][(tkc + 3) * BLEN + tnr] = tf32f(rb0.w);
            Bs[p][(tkc + 0) * BLEN + tnr + 64] = tf32f(rb1.x);
            Bs[p][(tkc + 1) * BLEN + tnr + 64] = tf32f(rb1.y);
            Bs[p][(tkc + 2) * BLEN + tnr + 64] = tf32f(rb1.z);
            Bs[p][(tkc + 3) * BLEN + tnr + 64] = tf32f(rb1.w);
        }
    };
    auto compute = [&](int p) {
        #pragma unroll
        for (int ks = 0; ks < 2; ks++) {
            const int kk = ks * 8;
            unsigned af[4][4], bf[4][2];
            #pragma unroll
            for (int i = 0; i < 4; i++) {
                int r0 = wm + i * 16 + g;
                af[i][0] = __float_as_uint(As[p][(r0    ) * ALEN + kk + t]);
                af[i][1] = __float_as_uint(As[p][(r0 + 8) * ALEN + kk + t]);
                af[i][2] = __float_as_uint(As[p][(r0    ) * ALEN + kk + t + 4]);
                af[i][3] = __float_as_uint(As[p][(r0 + 8) * ALEN + kk + t + 4]);
            }
            #pragma unroll
            for (int j = 0; j < 4; j++) {
                int c0 = wn + j * 8 + g;
                bf[j][0] = __float_as_uint(Bs[p][(kk + t    ) * BLEN + c0]);
                bf[j][1] = __float_as_uint(Bs[p][(kk + t + 4) * BLEN + c0]);
            }
            #pragma unroll
            for (int i = 0; i < 4; i++)
                #pragma unroll
                for (int j = 0; j < 4; j++)
                    mma_tf32(acc[i][j], af[i], bf[j]);
        }
    };

    const int nk = K / BK;
    loadG(0);
    storeS(0);
    __syncthreads();
    for (int kt = 0; kt < nk; kt++) {
        const int p = kt & 1;
        if (kt + 1 < nk) loadG((kt + 1) * BK);
        compute(p);
        if (kt + 1 < nk) {
            storeS(p ^ 1);
            __syncthreads();
        }
    }

    // Epilogue: each acc tile -> 2 float2 stores
    #pragma unroll
    for (int i = 0; i < 4; i++) {
        #pragma unroll
        for (int j = 0; j < 4; j++) {
            const long long row = bm + wm + i * 16 + g;
            const int       col = bn + wn + j * 8 + 2 * t;
            float2 v0 = make_float2(acc[i][j][0] * alpha, acc[i][j][1] * alpha);
            float2 v1 = make_float2(acc[i][j][2] * alpha, acc[i][j][3] * alpha);
            float* cp0 = &C[row * (long long)ldc + col];
            float* cp1 = &C[(row + 8) * (long long)ldc + col];
            if (EPI == 0) {
                *(float2*)cp0 = v0;
                *(float2*)cp1 = v1;
            } else if (EPI == 1) {
                float2 bb = *(const float2*)&bias[col];
                float2 o0 = *(const float2*)cp0;
                float2 o1 = *(const float2*)cp1;
                o0.x += v0.x + bb.x; o0.y += v0.y + bb.y;
                o1.x += v1.x + bb.x; o1.y += v1.y + bb.y;
                *(float2*)cp0 = o0;
                *(float2*)cp1 = o1;
            } else if (EPI == 2) {
                const float c = 0.70710678118654752f;
                v0.x = 0.5f * v0.x * erfcf(-v0.x * c);
                v0.y = 0.5f * v0.y * erfcf(-v0.y * c);
                v1.x = 0.5f * v1.x * erfcf(-v1.x * c);
                v1.y = 0.5f * v1.y * erfcf(-v1.y * c);
                *(float2*)cp0 = v0;
                *(float2*)cp1 = v1;
            } else {
                float2 o0 = *(const float2*)cp0;
                float2 o1 = *(const float2*)cp1;
                o0.x += v0.x; o0.y += v0.y;
                o1.x += v1.x; o1.y += v1.y;
                *(float2*)cp0 = o0;
                *(float2*)cp1 = o1;
            }
        }
    }
}

// ---------------------------------------------------------------- LayerNorm
__global__ __launch_bounds__(256) void ln_k(
    const float* __restrict__ x, const float* __restrict__ g,
    const float* __restrict__ b, float* __restrict__ out)
{
    __shared__ float sm0[8], sm1[8];
    const int row = blockIdx.x, tid = threadIdx.x;
    float4 v = ((const float4*)(x + (long long)row * Dd))[tid];
    float s  = v.x + v.y + v.z + v.w;
    float s2 = v.x * v.x + v.y * v.y + v.z * v.z + v.w * v.w;
    #pragma unroll
    for (int o = 16; o > 0; o >>= 1) {
        s  += __shfl_xor_sync(0xffffffffu, s,  o);
        s2 += __shfl_xor_sync(0xffffffffu, s2, o);
    }
    if ((tid & 31) == 0) { sm0[tid >> 5] = s; sm1[tid >> 5] = s2; }
    __syncthreads();
    if (tid < 32) {
        s  = (tid < 8) ? sm0[tid] : 0.f;
        s2 = (tid < 8) ? sm1[tid] : 0.f;
        #pragma unroll
        for (int o = 4; o > 0; o >>= 1) {
            s  += __shfl_xor_sync(0xffffffffu, s,  o);
            s2 += __shfl_xor_sync(0xffffffffu, s2, o);
        }
        if (tid == 0) { sm0[0] = s; sm1[0] = s2; }
    }
    __syncthreads();
    const float mean = sm0[0] * (1.f / Dd);
    const float var  = sm1[0] * (1.f / Dd) - mean * mean;
    const float rstd = rsqrtf(var + 1e-5f);
    float4 gg = ((const float4*)g)[tid];
    float4 bb = ((const float4*)b)[tid];
    float4 o;
    o.x = (v.x - mean) * rstd * gg.x + bb.x;
    o.y = (v.y - mean) * rstd * gg.y + bb.y;
    o.z = (v.z - mean) * rstd * gg.z + bb.z;
    o.w = (v.w - mean) * rstd * gg.w + bb.w;
    ((float4*)(out + (long long)row * Dd))[tid] = o;
}

// ---------------------------------------------------------------- Softmax (causal row)
__global__ __launch_bounds__(256) void softmax_k(float* __restrict__ attn)
{
    __shared__ float sm[8];
    const int row = blockIdx.x;
    const int q   = row & (Ss - 1);
    float* p = attn + (long long)row * Ss;
    const int tid = threadIdx.x;
    const int k0  = tid * 4;
    float4 v = ((const float4*)p)[tid];

    float m = -1e30f;
    if (k0 + 0 <= q) m = fmaxf(m, v.x);
    if (k0 + 1 <= q) m = fmaxf(m, v.y);
    if (k0 + 2 <= q) m = fmaxf(m, v.z);
    if (k0 + 3 <= q) m = fmaxf(m, v.w);
    #pragma unroll
    for (int o = 16; o > 0; o >>= 1) m = fmaxf(m, __shfl_xor_sync(0xffffffffu, m, o));
    if ((tid & 31) == 0) sm[tid >> 5] = m;
    __syncthreads();
    if (tid < 32) {
        float t = (tid < 8) ? sm[tid] : -1e30f;
        #pragma unroll
        for (int o = 4; o > 0; o >>= 1) t = fmaxf(t, __shfl_xor_sync(0xffffffffu, t, o));
        if (tid == 0) sm[0] = t;
    }
    __syncthreads();
    m = sm[0];
    __syncthreads();

    float4 e;
    e.x = (k0 + 0 <= q) ? __expf(v.x - m) : 0.f;
    e.y = (k0 + 1 <= q) ? __expf(v.y - m) : 0.f;
    e.z = (k0 + 2 <= q) ? __expf(v.z - m) : 0.f;
    e.w = (k0 + 3 <= q) ? __expf(v.w - m) : 0.f;
    float s = e.x + e.y + e.z + e.w;
    #pragma unroll
    for (int o = 16; o > 0; o >>= 1) s += __shfl_xor_sync(0xffffffffu, s, o);
    if ((tid & 31) == 0) sm[tid >> 5] = s;
    __syncthreads();
    if (tid < 32) {
        float t = (tid < 8) ? sm[tid] : 0.f;
        #pragma unroll
        for (int o = 4; o > 0; o >>= 1) t += __shfl_xor_sync(0xffffffffu, t, o);
        if (tid == 0) sm[0] = t;
    }
    __syncthreads();
    const float inv = 1.f / sm[0];
    e.x *= inv; e.y *= inv; e.z *= inv; e.w *= inv;
    ((float4*)p)[tid] = e;
}

// ---------------------------------------------------------------- Column sums (deterministic 2-stage)
__global__ __launch_bounds__(256) void colsum_part_k(
    const float* __restrict__ attn, float* __restrict__ part)
{
    const int k  = blockIdx.x * 256 + threadIdx.x;   // 0..1023
    const int b  = blockIdx.y;
    const int rs = blockIdx.z;
    const int RC = Hh * Ss / RSPLIT;                 // 256 rows per split
    const float* base = attn + (long long)b * Hh * Ss * Ss
                             + (long long)rs * RC * Ss + k;
    float s = 0.f;
    #pragma unroll 8
    for (int r = 0; r < RC; r++) s += base[(long long)r * Ss];
    part[(rs * Bb + b) * Ss + k] = s;
}

__global__ __launch_bounds__(256) void colsum_fin_k(
    const float* __restrict__ part, float* __restrict__ amap)
{
    const int i = blockIdx.x * 256 + threadIdx.x;    // 0..2047 (b*S+k)
    float s = 0.f;
    #pragma unroll
    for (int rs = 0; rs < RSPLIT; rs++) s += part[rs * Bb * Ss + i];
    amap[i] += s;
}

// ---------------------------------------------------------------- misc
__global__ __launch_bounds__(256) void save_ctx_k(
    const float* __restrict__ x, float4* __restrict__ st, int layer)
{
    const int i  = blockIdx.x * 256 + threadIdx.x;   // over BS*D/4
    const int d4 = i & 255;
    const int bs = i >> 8;
    st[((long long)bs * DEPTH + layer) * 256 + d4] = ((const float4*)x)[i];
}

__global__ void zero_k(float* p, int n)
{
    int i = blockIdx.x * 256 + threadIdx.x;
    if (i < n) p[i] = 0.f;
}

// ---------------------------------------------------------------- launcher
extern "C" void kernel_launch(void* const* d_in, const int* in_sizes, int n_in,
                              void* d_out, int out_size)
{
    const float* token = (const float*)d_in[0];
    const float* Wq    = (const float*)d_in[1];
    const float* Wkv   = (const float*)d_in[2];
    const float* Wo    = (const float*)d_in[3];
    const float* b_o   = (const float*)d_in[4];
    const float* g1    = (const float*)d_in[5];
    const float* b1    = (const float*)d_in[6];
    const float* g3    = (const float*)d_in[7];
    const float* b3    = (const float*)d_in[8];
    const float* W1    = (const float*)d_in[9];
    const float* W2    = (const float*)d_in[10];
    const float* gout  = (const float*)d_in[11];
    const float* bout  = (const float*)d_in[12];
    float* out = (float*)d_out;

    float *x, *xn, *q, *kv, *attn, *y, *ff, *part;
    cudaGetSymbolAddress((void**)&x,    g_x);
    cudaGetSymbolAddress((void**)&xn,   g_xn);
    cudaGetSymbolAddress((void**)&q,    g_q);
    cudaGetSymbolAddress((void**)&kv,   g_kv);
    cudaGetSymbolAddress((void**)&attn, g_attn);
    cudaGetSymbolAddress((void**)&y,    g_y);
    cudaGetSymbolAddress((void**)&ff,   g_ff);
    cudaGetSymbolAddress((void**)&part, g_part);

    float* out_state = out + (size_t)BS * Dd;
    float* amap      = out_state + (size_t)BS * DEPTH * Dd;

    cudaMemcpyAsync(x, token, sizeof(float) * BS * Dd, cudaMemcpyDeviceToDevice, 0);
    zero_k<<<(BS + 255) / 256, 256>>>(amap, BS);

    const float scale = rsqrtf((float)HD);

    for (int l = 0; l < DEPTH; l++) {
        // context snapshot
        save_ctx_k<<<BS * Dd / 4 / 256, 256>>>(x, (float4*)out_state, l);
        // LN1
        ln_k<<<BS, 256>>>(x, g1 + l * Dd, b1 + l * Dd, xn);
        // Q = xn @ Wq
        gemm_tc<0, false><<<dim3(Dd / BN, BS / BM, 1), 256>>>(
            xn, Wq + (size_t)l * Dd * Dd, q, nullptr,
            Dd, Dd, Dd, Dd, 0, 0, 0, 0, 0, 0, 1, 1.f, 0);
        // KV = xn @ Wkv
        gemm_tc<0, false><<<dim3(2 * Dd / BN, BS / BM, 1), 256>>>(
            xn, Wkv + (size_t)l * Dd * 2 * Dd, kv, nullptr,
            Dd, Dd, 2 * Dd, 2 * Dd, 0, 0, 0, 0, 0, 0, 1, 1.f, 0);
        // scores = scale * Q @ K^T  (batched over b,h; causal tile-skip)
        gemm_tc<0, true><<<dim3(Ss / BN, Ss / BM, Bb * Hh), 256>>>(
            q, kv, attn, nullptr,
            HD, Dd, 2 * Dd, Ss,
            (long long)Ss * Dd, HD,
            (long long)Ss * 2 * Dd, HD,
            (long long)Hh * Ss * Ss, (long long)Ss * Ss,
            Hh, scale, 1);
        // softmax rows (mask + normalize + zero upper triangle)
        softmax_k<<<Bb * Hh * Ss, 256>>>(attn);
        // attention-map column sums
        colsum_part_k<<<dim3(Ss / 256, Bb, RSPLIT), 256>>>(attn, part);
        colsum_fin_k<<<Bb * Ss / 256, 256>>>(part, amap);
        // y = attn @ V
        gemm_tc<0, false><<<dim3(HD / BN, Ss / BM, Bb * Hh), 256>>>(
            attn, kv + Dd, y, nullptr,
            Ss, Ss, 2 * Dd, Dd,
            (long long)Hh * Ss * Ss, (long long)Ss * Ss,
            (long long)Ss * 2 * Dd, HD,
            (long long)Ss * Dd, HD,
            Hh, 1.f, 0);
        // x += y @ Wo + b_o
        gemm_tc<1, false><<<dim3(Dd / BN, BS / BM, 1), 256>>>(
            y, Wo + (size_t)l * Dd * Dd, x, b_o + l * Dd,
            Dd, Dd, Dd, Dd, 0, 0, 0, 0, 0, 0, 1, 1.f, 0);
        // LN2
        ln_k<<<BS, 256>>>(x, g3 + l * Dd, b3 + l * Dd, xn);
        // ff = gelu(xn @ W1)
        gemm_tc<2, false><<<dim3(FF / BN, BS / BM, 1), 256>>>(
            xn, W1 + (size_t)l * Dd * FF, ff, nullptr,
            Dd, Dd, FF, FF, 0, 0, 0, 0, 0, 0, 1, 1.f, 0);
        // x += ff @ W2
        gemm_tc<3, false><<<dim3(Dd / BN, BS / BM, 1), 256>>>(
            ff, W2 + (size_t)l * FF * Dd, x, nullptr,
            FF, FF, Dd, Dd, 0, 0, 0, 0, 0, 0, 1, 1.f, 0);
    }
    // final LN -> x_out
    ln_k<<<BS, 256>>>(x, gout, bout, out);
}

// round 3
// speedup vs baseline: 2.2980x; 1.0401x over previous
#include <cuda_runtime.h>
#include <math.h>

// Problem constants
constexpr int Bb    = 2;
constexpr int Ss    = 1024;
constexpr int Dd    = 1024;
constexpr int Hh    = 8;
constexpr int HD    = 128;
constexpr int DEPTH = 8;
constexpr int FF    = 4096;
constexpr int BS    = Bb * Ss;      // 2048
constexpr int RSPLIT = 32;

// Scratch (device globals: allocation-free)
__device__ float g_x  [BS * Dd];
__device__ float g_xn [BS * Dd];
__device__ float g_qkv[(size_t)BS * 3 * Dd];            // q | k | v packed
__device__ float g_wqkv[(size_t)DEPTH * Dd * 3 * Dd];   // [Wq | Wkv] packed, 96MB
__device__ float g_attn[(size_t)Bb * Hh * Ss * Ss];     // 64 MB
__device__ float g_y  [BS * Dd];
__device__ float g_ff [(size_t)BS * FF];                // 32 MB
__device__ float g_part[RSPLIT * Bb * Ss];

// ---------------------------------------------------------------- tf32 helpers
__device__ __forceinline__ unsigned f2tf32(float x) {
    unsigned r;
    asm("cvt.rna.tf32.f32 %0, %1;" : "=r"(r) : "f"(x));
    return r;
}
__device__ __forceinline__ float tf32f(float x) {
    return __uint_as_float(f2tf32(x));
}

__device__ __forceinline__ void mma_tf32(float* c, const unsigned* a, const unsigned* b) {
    asm volatile(
        "mma.sync.aligned.m16n8k8.row.col.f32.tf32.tf32.f32 "
        "{%0,%1,%2,%3}, {%4,%5,%6,%7}, {%8,%9}, {%0,%1,%2,%3};"
        : "+f"(c[0]), "+f"(c[1]), "+f"(c[2]), "+f"(c[3])
        : "r"(a[0]), "r"(a[1]), "r"(a[2]), "r"(a[3]), "r"(b[0]), "r"(b[1]));
}

__device__ __forceinline__ void ldsm4(unsigned& r0, unsigned& r1, unsigned& r2,
                                      unsigned& r3, unsigned addr) {
    asm volatile("ldmatrix.sync.aligned.m8n8.x4.shared.b16 {%0,%1,%2,%3}, [%4];"
                 : "=r"(r0), "=r"(r1), "=r"(r2), "=r"(r3) : "r"(addr));
}

// ---------------------------------------------------------------- tensor-core GEMM
// C[M,N] = epilogue(alpha * A[M,K] @ B[K,N])
// TRANSB: B stored [N,K] row-major, i.e. C = A @ B^T
// EPI: 0 = store, 1 = C += acc + bias[col], 2 = store gelu(acc), 3 = C += acc
// causal: 0 none, 1 = skip tiles fully above diagonal (scores), 2 = K-trim (A·V)
#define BM 128
#define BN 128
#define BK 16
#define ALEN 20     // As row length; 80B rows: 16B-aligned + conflict-free ldmatrix
#define BLEN 132    // Bs row length

template<int EPI, bool TRANSB>
__global__ __launch_bounds__(256) void gemm_tc(
    const float* __restrict__ A, const float* __restrict__ Bg,
    float* __restrict__ C, const float* __restrict__ bias,
    int K, int lda, int ldb, int ldc,
    long long sAo, long long sAi, long long sBo, long long sBi,
    long long sCo, long long sCi, int zdiv,
    float alpha, int causal)
{
    const int bm = blockIdx.y * BM;
    const int bn = blockIdx.x * BN;
    if (causal == 1 && bn >= bm + BM) return;     // fully above causal diagonal
    const int Keff = (causal == 2) ? min(K, bm + BM) : K;

    const int z  = blockIdx.z;
    const int zo = z / zdiv;
    const int zi = z - zo * zdiv;
    A  += zo * sAo + zi * sAi;
    Bg += zo * sBo + zi * sBi;
    C  += zo * sCo + zi * sCi;

    __shared__ __align__(16) float As[2][BM * ALEN];   // [m][k]
    __shared__ __align__(16) float Bs[2][BK * BLEN];   // [k][n]

    const int tid  = threadIdx.x;
    const int lane = tid & 31;
    const int warp = tid >> 5;
    const int wm   = (warp & 1) * 64;      // warp tile 64(M) x 32(N)
    const int wn   = (warp >> 1) * 32;
    const int g    = lane >> 2;            // 0..7
    const int t    = lane & 3;             // 0..3

    // ldmatrix per-lane offset: piece p = lane/8, row r = lane%8
    const int lp = lane >> 3;
    const int lr = lane & 7;
    const int aRowOff = (lp & 1) * 8 + lr;
    const int aColOff = (lp >> 1) * 4;
    const unsigned asb0 = (unsigned)__cvta_generic_to_shared(&As[0][0]);
    const unsigned asb1 = (unsigned)__cvta_generic_to_shared(&As[1][0]);

    float acc[4][4][4];
    #pragma unroll
    for (int i = 0; i < 4; i++)
        #pragma unroll
        for (int j = 0; j < 4; j++)
            #pragma unroll
            for (int r = 0; r < 4; r++) acc[i][j][r] = 0.f;

    // global-load mappings
    const int arow = tid >> 2;             // 0..63 (+64 for second)
    const int ac4  = (tid & 3) * 4;        // k offset
    const int bkr  = tid >> 5;             // 0..7 (+8)
    const int bnc  = (tid & 31) * 4;       // n offset
    const int tnr  = tid >> 2;             // 0..63 (+64)
    const int tkc  = (tid & 3) * 4;        // k offset

    float4 ra0, ra1, rb0, rb1;

    auto loadG = [&](int k0) {
        ra0 = *(const float4*)&A[(long long)(bm + arow) * lda + k0 + ac4];
        ra1 = *(const float4*)&A[(long long)(bm + arow + 64) * lda + k0 + ac4];
        if (!TRANSB) {
            rb0 = *(const float4*)&Bg[(long long)(k0 + bkr) * ldb + bn + bnc];
            rb1 = *(const float4*)&Bg[(long long)(k0 + bkr + 8) * ldb + bn + bnc];
        } else {
            rb0 = *(const float4*)&Bg[(long long)(bn + tnr) * ldb + k0 + tkc];
            rb1 = *(const float4*)&Bg[(long long)(bn + tnr + 64) * ldb + k0 + tkc];
        }
    };
    auto storeS = [&](int p) {
        float* a0 = &As[p][arow * ALEN + ac4];
        a0[0] = tf32f(ra0.x); a0[1] = tf32f(ra0.y); a0[2] = tf32f(ra0.z); a0[3] = tf32f(ra0.w);
        float* a1 = &As[p][(arow + 64) * ALEN + ac4];
        a1[0] = tf32f(ra1.x); a1[1] = tf32f(ra1.y); a1[2] = tf32f(ra1.z); a1[3] = tf32f(ra1.w);
        if (!TRANSB) {
            float* s0 = &Bs[p][bkr * BLEN + bnc];
            s0[0] = tf32f(rb0.x); s0[1] = tf32f(rb0.y); s0[2] = tf32f(rb0.z); s0[3] = tf32f(rb0.w);
            float* s1 = &Bs[p][(bkr + 8) * BLEN + bnc];
            s1[0] = tf32f(rb1.x); s1[1] = tf32f(rb1.y); s1[2] = tf32f(rb1.z); s1[3] = tf32f(rb1.w);
        } else {
            Bs[p][(tkc + 0) * BLEN + tnr] = tf32f(rb0.x);
            Bs[p][(tkc + 1) * BLEN + tnr] = tf32f(rb0.y);
            Bs[p][(tkc + 2) * BLEN + tnr] = tf32f(rb0.z);
            Bs[p][(tkc + 3) * BLEN + tnr] = tf32f(rb0.w);
            Bs[p][(tkc + 0) * BLEN + tnr + 64] = tf32f(rb1.x);
            Bs[p][(tkc + 1) * BLEN + tnr + 64] = tf32f(rb1.y);
            Bs[p][(tkc + 2) * BLEN + tnr + 64] = tf32f(rb1.z);
            Bs[p][(tkc + 3) * BLEN + tnr + 64] = tf32f(rb1.w);
        }
    };
    auto compute = [&](int p) {
        const unsigned abase = (p ? asb1 : asb0)
                             + ((wm + aRowOff) * ALEN + aColOff) * 4;
        #pragma unroll
        for (int ks = 0; ks < 2; ks++) {
            const int kk = ks * 8;
            unsigned af[4][4], bf[4][2];
            #pragma unroll
            for (int i = 0; i < 4; i++)
                ldsm4(af[i][0], af[i][1], af[i][2], af[i][3],
                      abase + (unsigned)((i * 16 * ALEN + kk) * 4));
            #pragma unroll
            for (int j = 0; j < 4; j++) {
                int c0 = wn + j * 8 + g;
                bf[j][0] = __float_as_uint(Bs[p][(kk + t    ) * BLEN + c0]);
                bf[j][1] = __float_as_uint(Bs[p][(kk + t + 4) * BLEN + c0]);
            }
            #pragma unroll
            for (int i = 0; i < 4; i++)
                #pragma unroll
                for (int j = 0; j < 4; j++)
                    mma_tf32(acc[i][j], af[i], bf[j]);
        }
    };

    const int nk = Keff / BK;
    loadG(0);
    storeS(0);
    __syncthreads();
    for (int kt = 0; kt < nk; kt++) {
        const int p = kt & 1;
        if (kt + 1 < nk) loadG((kt + 1) * BK);
        compute(p);
        if (kt + 1 < nk) {
            storeS(p ^ 1);
            __syncthreads();
        }
    }

    // Epilogue
    #pragma unroll
    for (int i = 0; i < 4; i++) {
        #pragma unroll
        for (int j = 0; j < 4; j++) {
            const long long row = bm + wm + i * 16 + g;
            const int       col = bn + wn + j * 8 + 2 * t;
            float2 v0 = make_float2(acc[i][j][0] * alpha, acc[i][j][1] * alpha);
            float2 v1 = make_float2(acc[i][j][2] * alpha, acc[i][j][3] * alpha);
            float* cp0 = &C[row * (long long)ldc + col];
            float* cp1 = &C[(row + 8) * (long long)ldc + col];
            if (EPI == 0) {
                *(float2*)cp0 = v0;
                *(float2*)cp1 = v1;
            } else if (EPI == 1) {
                float2 bb = *(const float2*)&bias[col];
                float2 o0 = *(const float2*)cp0;
                float2 o1 = *(const float2*)cp1;
                o0.x += v0.x + bb.x; o0.y += v0.y + bb.y;
                o1.x += v1.x + bb.x; o1.y += v1.y + bb.y;
                *(float2*)cp0 = o0;
                *(float2*)cp1 = o1;
            } else if (EPI == 2) {
                const float c = 0.70710678118654752f;
                v0.x = 0.5f * v0.x * erfcf(-v0.x * c);
                v0.y = 0.5f * v0.y * erfcf(-v0.y * c);
                v1.x = 0.5f * v1.x * erfcf(-v1.x * c);
                v1.y = 0.5f * v1.y * erfcf(-v1.y * c);
                *(float2*)cp0 = v0;
                *(float2*)cp1 = v1;
            } else {
                float2 o0 = *(const float2*)cp0;
                float2 o1 = *(const float2*)cp1;
                o0.x += v0.x; o0.y += v0.y;
                o1.x += v1.x; o1.y += v1.y;
                *(float2*)cp0 = o0;
                *(float2*)cp1 = o1;
            }
        }
    }
}

// ---------------------------------------------------------------- weight pack
__global__ __launch_bounds__(256) void pack_w(
    const float4* __restrict__ Wq, const float4* __restrict__ Wkv,
    float4* __restrict__ wqkv)
{
    const long long i = (long long)blockIdx.x * 256 + threadIdx.x;   // DEPTH*D*3D/4
    const int C4 = 3 * Dd / 4;                                       // 768
    const long long row = i / C4;                                    // l*D + d
    const int c4 = (int)(i - row * C4);
    float4 v = (c4 < Dd / 4) ? Wq[row * (Dd / 4) + c4]
                             : Wkv[row * (2 * Dd / 4) + (c4 - Dd / 4)];
    wqkv[i] = v;
}

// ---------------------------------------------------------------- LayerNorm
__global__ __launch_bounds__(256) void ln_k(
    const float* __restrict__ x, const float* __restrict__ g,
    const float* __restrict__ b, float* __restrict__ out)
{
    __shared__ float sm0[8], sm1[8];
    const int row = blockIdx.x, tid = threadIdx.x;
    float4 v = ((const float4*)(x + (long long)row * Dd))[tid];
    float s  = v.x + v.y + v.z + v.w;
    float s2 = v.x * v.x + v.y * v.y + v.z * v.z + v.w * v.w;
    #pragma unroll
    for (int o = 16; o > 0; o >>= 1) {
        s  += __shfl_xor_sync(0xffffffffu, s,  o);
        s2 += __shfl_xor_sync(0xffffffffu, s2, o);
    }
    if ((tid & 31) == 0) { sm0[tid >> 5] = s; sm1[tid >> 5] = s2; }
    __syncthreads();
    if (tid < 32) {
        s  = (tid < 8) ? sm0[tid] : 0.f;
        s2 = (tid < 8) ? sm1[tid] : 0.f;
        #pragma unroll
        for (int o = 4; o > 0; o >>= 1) {
            s  += __shfl_xor_sync(0xffffffffu, s,  o);
            s2 += __shfl_xor_sync(0xffffffffu, s2, o);
        }
        if (tid == 0) { sm0[0] = s; sm1[0] = s2; }
    }
    __syncthreads();
    const float mean = sm0[0] * (1.f / Dd);
    const float var  = sm1[0] * (1.f / Dd) - mean * mean;
    const float rstd = rsqrtf(var + 1e-5f);
    float4 gg = ((const float4*)g)[tid];
    float4 bb = ((const float4*)b)[tid];
    float4 o;
    o.x = (v.x - mean) * rstd * gg.x + bb.x;
    o.y = (v.y - mean) * rstd * gg.y + bb.y;
    o.z = (v.z - mean) * rstd * gg.z + bb.z;
    o.w = (v.w - mean) * rstd * gg.w + bb.w;
    ((float4*)(out + (long long)row * Dd))[tid] = o;
}

// ---------------------------------------------------------------- Softmax (causal row)
__global__ __launch_bounds__(256) void softmax_k(float* __restrict__ attn)
{
    __shared__ float sm[8];
    const int row = blockIdx.x;
    const int q   = row & (Ss - 1);
    float* p = attn + (long long)row * Ss;
    const int tid = threadIdx.x;
    const int k0  = tid * 4;
    float4 v = ((const float4*)p)[tid];

    float m = -1e30f;
    if (k0 + 0 <= q) m = fmaxf(m, v.x);
    if (k0 + 1 <= q) m = fmaxf(m, v.y);
    if (k0 + 2 <= q) m = fmaxf(m, v.z);
    if (k0 + 3 <= q) m = fmaxf(m, v.w);
    #pragma unroll
    for (int o = 16; o > 0; o >>= 1) m = fmaxf(m, __shfl_xor_sync(0xffffffffu, m, o));
    if ((tid & 31) == 0) sm[tid >> 5] = m;
    __syncthreads();
    if (tid < 32) {
        float t = (tid < 8) ? sm[tid] : -1e30f;
        #pragma unroll
        for (int o = 4; o > 0; o >>= 1) t = fmaxf(t, __shfl_xor_sync(0xffffffffu, t, o));
        if (tid == 0) sm[0] = t;
    }
    __syncthreads();
    m = sm[0];
    __syncthreads();

    float4 e;
    e.x = (k0 + 0 <= q) ? __expf(v.x - m) : 0.f;
    e.y = (k0 + 1 <= q) ? __expf(v.y - m) : 0.f;
    e.z = (k0 + 2 <= q) ? __expf(v.z - m) : 0.f;
    e.w = (k0 + 3 <= q) ? __expf(v.w - m) : 0.f;
    float s = e.x + e.y + e.z + e.w;
    #pragma unroll
    for (int o = 16; o > 0; o >>= 1) s += __shfl_xor_sync(0xffffffffu, s, o);
    if ((tid & 31) == 0) sm[tid >> 5] = s;
    __syncthreads();
    if (tid < 32) {
        float t = (tid < 8) ? sm[tid] : 0.f;
        #pragma unroll
        for (int o = 4; o > 0; o >>= 1) t += __shfl_xor_sync(0xffffffffu, t, o);
        if (tid == 0) sm[0] = t;
    }
    __syncthreads();
    const float inv = 1.f / sm[0];
    e.x *= inv; e.y *= inv; e.z *= inv; e.w *= inv;
    ((float4*)p)[tid] = e;
}

// ---------------------------------------------------------------- Column sums
__global__ __launch_bounds__(256) void colsum_part_k(
    const float* __restrict__ attn, float* __restrict__ part)
{
    const int k  = blockIdx.x * 256 + threadIdx.x;   // 0..1023
    const int b  = blockIdx.y;
    const int rs = blockIdx.z;
    const int RC = Hh * Ss / RSPLIT;                 // 256 rows per split
    const float* base = attn + (long long)b * Hh * Ss * Ss
                             + (long long)rs * RC * Ss + k;
    float s = 0.f;
    #pragma unroll 8
    for (int r = 0; r < RC; r++) s += base[(long long)r * Ss];
    part[(rs * Bb + b) * Ss + k] = s;
}

__global__ __launch_bounds__(256) void colsum_fin_k(
    const float* __restrict__ part, float* __restrict__ amap)
{
    const int i = blockIdx.x * 256 + threadIdx.x;    // 0..2047
    float s = 0.f;
    #pragma unroll
    for (int rs = 0; rs < RSPLIT; rs++) s += part[rs * Bb * Ss + i];
    amap[i] += s;
}

// ---------------------------------------------------------------- misc
__global__ __launch_bounds__(256) void save_ctx_k(
    const float* __restrict__ x, float4* __restrict__ st, int layer)
{
    const int i  = blockIdx.x * 256 + threadIdx.x;   // over BS*D/4
    const int d4 = i & 255;
    const int bs = i >> 8;
    st[((long long)bs * DEPTH + layer) * 256 + d4] = ((const float4*)x)[i];
}

__global__ void zero_k(float* p, int n)
{
    int i = blockIdx.x * 256 + threadIdx.x;
    if (i < n) p[i] = 0.f;
}

// ---------------------------------------------------------------- launcher
extern "C" void kernel_launch(void* const* d_in, const int* in_sizes, int n_in,
                              void* d_out, int out_size)
{
    const float* token = (const float*)d_in[0];
    const float* Wq    = (const float*)d_in[1];
    const float* Wkv   = (const float*)d_in[2];
    const float* Wo    = (const float*)d_in[3];
    const float* b_o   = (const float*)d_in[4];
    const float* g1    = (const float*)d_in[5];
    const float* b1    = (const float*)d_in[6];
    const float* g3    = (const float*)d_in[7];
    const float* b3    = (const float*)d_in[8];
    const float* W1    = (const float*)d_in[9];
    const float* W2    = (const float*)d_in[10];
    const float* gout  = (const float*)d_in[11];
    const float* bout  = (const float*)d_in[12];
    float* out = (float*)d_out;

    float *x, *xn, *qkv, *wqkv, *attn, *y, *ff, *part;
    cudaGetSymbolAddress((void**)&x,    g_x);
    cudaGetSymbolAddress((void**)&xn,   g_xn);
    cudaGetSymbolAddress((void**)&qkv,  g_qkv);
    cudaGetSymbolAddress((void**)&wqkv, g_wqkv);
    cudaGetSymbolAddress((void**)&attn, g_attn);
    cudaGetSymbolAddress((void**)&y,    g_y);
    cudaGetSymbolAddress((void**)&ff,   g_ff);
    cudaGetSymbolAddress((void**)&part, g_part);

    float* out_state = out + (size_t)BS * Dd;
    float* amap      = out_state + (size_t)BS * DEPTH * Dd;

    cudaMemcpyAsync(x, token, sizeof(float) * BS * Dd, cudaMemcpyDeviceToDevice, 0);
    zero_k<<<(BS + 255) / 256, 256>>>(amap, BS);
    pack_w<<<DEPTH * Dd * 3 * Dd / 4 / 256, 256>>>(
        (const float4*)Wq, (const float4*)Wkv, (float4*)wqkv);

    const float scale = rsqrtf((float)HD);
    const int D3 = 3 * Dd;

    for (int l = 0; l < DEPTH; l++) {
        // context snapshot
        save_ctx_k<<<BS * Dd / 4 / 256, 256>>>(x, (float4*)out_state, l);
        // LN1
        ln_k<<<BS, 256>>>(x, g1 + l * Dd, b1 + l * Dd, xn);
        // QKV = xn @ [Wq|Wkv]   (N=3072 -> 384 CTAs)
        gemm_tc<0, false><<<dim3(D3 / BN, BS / BM, 1), 256>>>(
            xn, wqkv + (size_t)l * Dd * D3, qkv, nullptr,
            Dd, Dd, D3, D3, 0, 0, 0, 0, 0, 0, 1, 1.f, 0);
        // scores = scale * Q @ K^T  (batched over b,h; causal tile-skip)
        gemm_tc<0, true><<<dim3(Ss / BN, Ss / BM, Bb * Hh), 256>>>(
            qkv, qkv + Dd, attn, nullptr,
            HD, D3, D3, Ss,
            (long long)Ss * D3, HD,
            (long long)Ss * D3, HD,
            (long long)Hh * Ss * Ss, (long long)Ss * Ss,
            Hh, scale, 1);
        // softmax rows (mask + normalize + zero upper triangle)
        softmax_k<<<Bb * Hh * Ss, 256>>>(attn);
        // attention-map column sums
        colsum_part_k<<<dim3(Ss / 256, Bb, RSPLIT), 256>>>(attn, part);
        colsum_fin_k<<<Bb * Ss / 256, 256>>>(part, amap);
        // y = attn @ V   (causal K-trim: rows only attend to k <= q)
        gemm_tc<0, false><<<dim3(HD / BN, Ss / BM, Bb * Hh), 256>>>(
            attn, qkv + 2 * Dd, y, nullptr,
            Ss, Ss, D3, Dd,
            (long long)Hh * Ss * Ss, (long long)Ss * Ss,
            (long long)Ss * D3, HD,
            (long long)Ss * Dd, HD,
            Hh, 1.f, 2);
        // x += y @ Wo + b_o
        gemm_tc<1, false><<<dim3(Dd / BN, BS / BM, 1), 256>>>(
            y, Wo + (size_t)l * Dd * Dd, x, b_o + l * Dd,
            Dd, Dd, Dd, Dd, 0, 0, 0, 0, 0, 0, 1, 1.f, 0);
        // LN2
        ln_k<<<BS, 256>>>(x, g3 + l * Dd, b3 + l * Dd, xn);
        // ff = gelu(xn @ W1)
        gemm_tc<2, false><<<dim3(FF / BN, BS / BM, 1), 256>>>(
            xn, W1 + (size_t)l * Dd * FF, ff, nullptr,
            Dd, Dd, FF, FF, 0, 0, 0, 0, 0, 0, 1, 1.f, 0);
        // x += ff @ W2
        gemm_tc<3, false><<<dim3(Dd / BN, BS / BM, 1), 256>>>(
            ff, W2 + (size_t)l * FF * Dd, x, nullptr,
            FF, FF, Dd, Dd, 0, 0, 0, 0, 0, 0, 1, 1.f, 0);
    }
    // final LN -> x_out
    ln_k<<<BS, 256>>>(x, gout, bout, out);
}

// round 4
// speedup vs baseline: 2.5286x; 1.1003x over previous
#include <cuda_runtime.h>
#include <math.h>

// Problem constants
constexpr int Bb    = 2;
constexpr int Ss    = 1024;
constexpr int Dd    = 1024;
constexpr int Hh    = 8;
constexpr int HD    = 128;
constexpr int DEPTH = 8;
constexpr int FF    = 4096;
constexpr int BS    = Bb * Ss;      // 2048
constexpr int RSPLIT = 32;

// Scratch (device globals: allocation-free)
__device__ float g_x  [BS * Dd];
__device__ float g_xn [BS * Dd];
__device__ float g_qkv[(size_t)BS * 3 * Dd];            // q | k | v packed
__device__ float g_wqkv[(size_t)DEPTH * Dd * 3 * Dd];   // [Wq | Wkv] packed, 96MB
__device__ float g_attn[(size_t)Bb * Hh * Ss * Ss];     // 64 MB
__device__ float g_y  [BS * Dd];
__device__ float g_ff [(size_t)BS * FF];                // 32 MB
__device__ float g_red[(size_t)4 * BS * Dd];            // split-K partials, 32MB
__device__ float g_part[RSPLIT * Bb * Ss];

// ---------------------------------------------------------------- tf32 helpers
__device__ __forceinline__ unsigned f2tf32(float x) {
    unsigned r;
    asm("cvt.rna.tf32.f32 %0, %1;" : "=r"(r) : "f"(x));
    return r;
}
__device__ __forceinline__ float tf32f(float x) {
    return __uint_as_float(f2tf32(x));
}

__device__ __forceinline__ void mma_tf32(float* c, const unsigned* a, const unsigned* b) {
    asm volatile(
        "mma.sync.aligned.m16n8k8.row.col.f32.tf32.tf32.f32 "
        "{%0,%1,%2,%3}, {%4,%5,%6,%7}, {%8,%9}, {%0,%1,%2,%3};"
        : "+f"(c[0]), "+f"(c[1]), "+f"(c[2]), "+f"(c[3])
        : "r"(a[0]), "r"(a[1]), "r"(a[2]), "r"(a[3]), "r"(b[0]), "r"(b[1]));
}

__device__ __forceinline__ void ldsm4(unsigned& r0, unsigned& r1, unsigned& r2,
                                      unsigned& r3, unsigned addr) {
    asm volatile("ldmatrix.sync.aligned.m8n8.x4.shared.b16 {%0,%1,%2,%3}, [%4];"
                 : "=r"(r0), "=r"(r1), "=r"(r2), "=r"(r3) : "r"(addr));
}

// ---------------------------------------------------------------- tensor-core GEMM
// C[M,N] = epilogue(alpha * A[M,K] @ B[K,N])
// TRANSB: B stored [N,K] row-major, i.e. C = A @ B^T
// EPI: 0 = store, 1 = C += acc + bias[col], 2 = store gelu(acc), 3 = C += acc
// causal: 0 none, 1 = skip tiles fully above diagonal (scores), 2 = K-trim (A·V)
#define BM 128
#define BN 128
#define BK 16
#define ALEN 20     // As row length; 80B rows: 16B-aligned + conflict-free ldmatrix
#define BLEN 132    // Bs row length

template<int EPI, bool TRANSB>
__global__ __launch_bounds__(256, 2) void gemm_tc(
    const float* __restrict__ A, const float* __restrict__ Bg,
    float* __restrict__ C, const float* __restrict__ bias,
    int K, int lda, int ldb, int ldc,
    long long sAo, long long sAi, long long sBo, long long sBi,
    long long sCo, long long sCi, int zdiv,
    float alpha, int causal)
{
    const int bm = blockIdx.y * BM;
    const int bn = blockIdx.x * BN;
    if (causal == 1 && bn >= bm + BM) return;     // fully above causal diagonal
    const int Keff = (causal == 2) ? min(K, bm + BM) : K;

    const int z  = blockIdx.z;
    const int zo = z / zdiv;
    const int zi = z - zo * zdiv;
    A  += zo * sAo + zi * sAi;
    Bg += zo * sBo + zi * sBi;
    C  += zo * sCo + zi * sCi;

    __shared__ __align__(16) float As[2][BM * ALEN];   // [m][k]
    __shared__ __align__(16) float Bs[2][BK * BLEN];   // [k][n]

    const int tid  = threadIdx.x;
    const int lane = tid & 31;
    const int warp = tid >> 5;
    const int wm   = (warp & 1) * 64;      // warp tile 64(M) x 32(N)
    const int wn   = (warp >> 1) * 32;
    const int g    = lane >> 2;            // 0..7
    const int t    = lane & 3;             // 0..3

    // ldmatrix per-lane offset
    const int lp = lane >> 3;
    const int lr = lane & 7;
    const int aRowOff = (lp & 1) * 8 + lr;
    const int aColOff = (lp >> 1) * 4;
    const unsigned asb0 = (unsigned)__cvta_generic_to_shared(&As[0][0]);
    const unsigned asb1 = (unsigned)__cvta_generic_to_shared(&As[1][0]);

    float acc[4][4][4];
    #pragma unroll
    for (int i = 0; i < 4; i++)
        #pragma unroll
        for (int j = 0; j < 4; j++)
            #pragma unroll
            for (int r = 0; r < 4; r++) acc[i][j][r] = 0.f;

    // global-load mappings
    const int arow = tid >> 2;             // 0..63 (+64 for second)
    const int ac4  = (tid & 3) * 4;        // k offset
    const int bkr  = tid >> 5;             // 0..7 (+8)
    const int bnc  = (tid & 31) * 4;       // n offset
    const int tnr  = tid >> 2;             // 0..63 (+64)
    const int tkc  = (tid & 3) * 4;        // k offset

    float4 ra0, ra1, rb0, rb1;

    auto loadG = [&](int k0) {
        ra0 = *(const float4*)&A[(long long)(bm + arow) * lda + k0 + ac4];
        ra1 = *(const float4*)&A[(long long)(bm + arow + 64) * lda + k0 + ac4];
        if (!TRANSB) {
            rb0 = *(const float4*)&Bg[(long long)(k0 + bkr) * ldb + bn + bnc];
            rb1 = *(const float4*)&Bg[(long long)(k0 + bkr + 8) * ldb + bn + bnc];
        } else {
            rb0 = *(const float4*)&Bg[(long long)(bn + tnr) * ldb + k0 + tkc];
            rb1 = *(const float4*)&Bg[(long long)(bn + tnr + 64) * ldb + k0 + tkc];
        }
    };
    auto storeS = [&](int p) {
        float* a0 = &As[p][arow * ALEN + ac4];
        a0[0] = tf32f(ra0.x); a0[1] = tf32f(ra0.y); a0[2] = tf32f(ra0.z); a0[3] = tf32f(ra0.w);
        float* a1 = &As[p][(arow + 64) * ALEN + ac4];
        a1[0] = tf32f(ra1.x); a1[1] = tf32f(ra1.y); a1[2] = tf32f(ra1.z); a1[3] = tf32f(ra1.w);
        if (!TRANSB) {
            float* s0 = &Bs[p][bkr * BLEN + bnc];
            s0[0] = tf32f(rb0.x); s0[1] = tf32f(rb0.y); s0[2] = tf32f(rb0.z); s0[3] = tf32f(rb0.w);
            float* s1 = &Bs[p][(bkr + 8) * BLEN + bnc];
            s1[0] = tf32f(rb1.x); s1[1] = tf32f(rb1.y); s1[2] = tf32f(rb1.z); s1[3] = tf32f(rb1.w);
        } else {
            Bs[p][(tkc + 0) * BLEN + tnr] = tf32f(rb0.x);
            Bs[p][(tkc + 1) * BLEN + tnr] = tf32f(rb0.y);
            Bs[p][(tkc + 2) * BLEN + tnr] = tf32f(rb0.z);
            Bs[p][(tkc + 3) * BLEN + tnr] = tf32f(rb0.w);
            Bs[p][(tkc + 0) * BLEN + tnr + 64] = tf32f(rb1.x);
            Bs[p][(tkc + 1) * BLEN + tnr + 64] = tf32f(rb1.y);
            Bs[p][(tkc + 2) * BLEN + tnr + 64] = tf32f(rb1.z);
            Bs[p][(tkc + 3) * BLEN + tnr + 64] = tf32f(rb1.w);
        }
    };
    auto compute = [&](int p) {
        const unsigned abase = (p ? asb1 : asb0)
                             + ((wm + aRowOff) * ALEN + aColOff) * 4;
        #pragma unroll
        for (int ks = 0; ks < 2; ks++) {
            const int kk = ks * 8;
            unsigned af[4][4], bf[4][2];
            #pragma unroll
            for (int i = 0; i < 4; i++)
                ldsm4(af[i][0], af[i][1], af[i][2], af[i][3],
                      abase + (unsigned)((i * 16 * ALEN + kk) * 4));
            #pragma unroll
            for (int j = 0; j < 4; j++) {
                int c0 = wn + j * 8 + g;
                bf[j][0] = __float_as_uint(Bs[p][(kk + t    ) * BLEN + c0]);
                bf[j][1] = __float_as_uint(Bs[p][(kk + t + 4) * BLEN + c0]);
            }
            #pragma unroll
            for (int i = 0; i < 4; i++)
                #pragma unroll
                for (int j = 0; j < 4; j++)
                    mma_tf32(acc[i][j], af[i], bf[j]);
        }
    };

    const int nk = Keff / BK;
    loadG(0);
    storeS(0);
    __syncthreads();
    for (int kt = 0; kt < nk; kt++) {
        const int p = kt & 1;
        if (kt + 1 < nk) loadG((kt + 1) * BK);
        compute(p);
        if (kt + 1 < nk) {
            storeS(p ^ 1);
            __syncthreads();
        }
    }

    // Epilogue
    #pragma unroll
    for (int i = 0; i < 4; i++) {
        #pragma unroll
        for (int j = 0; j < 4; j++) {
            const long long row = bm + wm + i * 16 + g;
            const int       col = bn + wn + j * 8 + 2 * t;
            float2 v0 = make_float2(acc[i][j][0] * alpha, acc[i][j][1] * alpha);
            float2 v1 = make_float2(acc[i][j][2] * alpha, acc[i][j][3] * alpha);
            float* cp0 = &C[row * (long long)ldc + col];
            float* cp1 = &C[(row + 8) * (long long)ldc + col];
            if (EPI == 0) {
                *(float2*)cp0 = v0;
                *(float2*)cp1 = v1;
            } else if (EPI == 1) {
                float2 bb = *(const float2*)&bias[col];
                float2 o0 = *(const float2*)cp0;
                float2 o1 = *(const float2*)cp1;
                o0.x += v0.x + bb.x; o0.y += v0.y + bb.y;
                o1.x += v1.x + bb.x; o1.y += v1.y + bb.y;
                *(float2*)cp0 = o0;
                *(float2*)cp1 = o1;
            } else if (EPI == 2) {
                const float c = 0.70710678118654752f;
                v0.x = 0.5f * v0.x * erfcf(-v0.x * c);
                v0.y = 0.5f * v0.y * erfcf(-v0.y * c);
                v1.x = 0.5f * v1.x * erfcf(-v1.x * c);
                v1.y = 0.5f * v1.y * erfcf(-v1.y * c);
                *(float2*)cp0 = v0;
                *(float2*)cp1 = v1;
            } else {
                float2 o0 = *(const float2*)cp0;
                float2 o1 = *(const float2*)cp1;
                o0.x += v0.x; o0.y += v0.y;
                o1.x += v1.x; o1.y += v1.y;
                *(float2*)cp0 = o0;
                *(float2*)cp1 = o1;
            }
        }
    }
}

// ---------------------------------------------------------------- split-K reduce
// x[i] += sum_p part[p][i] (+ bias[col]);  fixed order -> deterministic
template<int P, bool BIAS>
__global__ __launch_bounds__(256) void reduce_add_k(
    const float4* __restrict__ part, float4* __restrict__ x,
    const float* __restrict__ bias)
{
    const int i = blockIdx.x * 256 + threadIdx.x;    // over BS*Dd/4
    constexpr int N4 = BS * Dd / 4;
    float4 s = part[i];
    #pragma unroll
    for (int p = 1; p < P; p++) {
        float4 v = part[(size_t)p * N4 + i];
        s.x += v.x; s.y += v.y; s.z += v.z; s.w += v.w;
    }
    if (BIAS) {
        float4 bb = ((const float4*)bias)[i & (Dd / 4 - 1)];
        s.x += bb.x; s.y += bb.y; s.z += bb.z; s.w += bb.w;
    }
    float4 o = x[i];
    o.x += s.x; o.y += s.y; o.z += s.z; o.w += s.w;
    x[i] = o;
}

// ---------------------------------------------------------------- weight pack
__global__ __launch_bounds__(256) void pack_w(
    const float4* __restrict__ Wq, const float4* __restrict__ Wkv,
    float4* __restrict__ wqkv)
{
    const long long i = (long long)blockIdx.x * 256 + threadIdx.x;   // DEPTH*D*3D/4
    const int C4 = 3 * Dd / 4;                                       // 768
    const long long row = i / C4;                                    // l*D + d
    const int c4 = (int)(i - row * C4);
    float4 v = (c4 < Dd / 4) ? Wq[row * (Dd / 4) + c4]
                             : Wkv[row * (2 * Dd / 4) + (c4 - Dd / 4)];
    wqkv[i] = v;
}

// ---------------------------------------------------------------- LayerNorm
__global__ __launch_bounds__(256) void ln_k(
    const float* __restrict__ x, const float* __restrict__ g,
    const float* __restrict__ b, float* __restrict__ out)
{
    __shared__ float sm0[8], sm1[8];
    const int row = blockIdx.x, tid = threadIdx.x;
    float4 v = ((const float4*)(x + (long long)row * Dd))[tid];
    float s  = v.x + v.y + v.z + v.w;
    float s2 = v.x * v.x + v.y * v.y + v.z * v.z + v.w * v.w;
    #pragma unroll
    for (int o = 16; o > 0; o >>= 1) {
        s  += __shfl_xor_sync(0xffffffffu, s,  o);
        s2 += __shfl_xor_sync(0xffffffffu, s2, o);
    }
    if ((tid & 31) == 0) { sm0[tid >> 5] = s; sm1[tid >> 5] = s2; }
    __syncthreads();
    if (tid < 32) {
        s  = (tid < 8) ? sm0[tid] : 0.f;
        s2 = (tid < 8) ? sm1[tid] : 0.f;
        #pragma unroll
        for (int o = 4; o > 0; o >>= 1) {
            s  += __shfl_xor_sync(0xffffffffu, s,  o);
            s2 += __shfl_xor_sync(0xffffffffu, s2, o);
        }
        if (tid == 0) { sm0[0] = s; sm1[0] = s2; }
    }
    __syncthreads();
    const float mean = sm0[0] * (1.f / Dd);
    const float var  = sm1[0] * (1.f / Dd) - mean * mean;
    const float rstd = rsqrtf(var + 1e-5f);
    float4 gg = ((const float4*)g)[tid];
    float4 bb = ((const float4*)b)[tid];
    float4 o;
    o.x = (v.x - mean) * rstd * gg.x + bb.x;
    o.y = (v.y - mean) * rstd * gg.y + bb.y;
    o.z = (v.z - mean) * rstd * gg.z + bb.z;
    o.w = (v.w - mean) * rstd * gg.w + bb.w;
    ((float4*)(out + (long long)row * Dd))[tid] = o;
}

// ---------------------------------------------------------------- Softmax (causal row)
__global__ __launch_bounds__(256) void softmax_k(float* __restrict__ attn)
{
    __shared__ float sm[8];
    const int row = blockIdx.x;
    const int q   = row & (Ss - 1);
    float* p = attn + (long long)row * Ss;
    const int tid = threadIdx.x;
    const int k0  = tid * 4;
    float4 v = ((const float4*)p)[tid];

    float m = -1e30f;
    if (k0 + 0 <= q) m = fmaxf(m, v.x);
    if (k0 + 1 <= q) m = fmaxf(m, v.y);
    if (k0 + 2 <= q) m = fmaxf(m, v.z);
    if (k0 + 3 <= q) m = fmaxf(m, v.w);
    #pragma unroll
    for (int o = 16; o > 0; o >>= 1) m = fmaxf(m, __shfl_xor_sync(0xffffffffu, m, o));
    if ((tid & 31) == 0) sm[tid >> 5] = m;
    __syncthreads();
    if (tid < 32) {
        float t = (tid < 8) ? sm[tid] : -1e30f;
        #pragma unroll
        for (int o = 4; o > 0; o >>= 1) t = fmaxf(t, __shfl_xor_sync(0xffffffffu, t, o));
        if (tid == 0) sm[0] = t;
    }
    __syncthreads();
    m = sm[0];
    __syncthreads();

    float4 e;
    e.x = (k0 + 0 <= q) ? __expf(v.x - m) : 0.f;
    e.y = (k0 + 1 <= q) ? __expf(v.y - m) : 0.f;
    e.z = (k0 + 2 <= q) ? __expf(v.z - m) : 0.f;
    e.w = (k0 + 3 <= q) ? __expf(v.w - m) : 0.f;
    float s = e.x + e.y + e.z + e.w;
    #pragma unroll
    for (int o = 16; o > 0; o >>= 1) s += __shfl_xor_sync(0xffffffffu, s, o);
    if ((tid & 31) == 0) sm[tid >> 5] = s;
    __syncthreads();
    if (tid < 32) {
        float t = (tid < 8) ? sm[tid] : 0.f;
        #pragma unroll
        for (int o = 4; o > 0; o >>= 1) t += __shfl_xor_sync(0xffffffffu, t, o);
        if (tid == 0) sm[0] = t;
    }
    __syncthreads();
    const float inv = 1.f / sm[0];
    e.x *= inv; e.y *= inv; e.z *= inv; e.w *= inv;
    ((float4*)p)[tid] = e;
}

// ---------------------------------------------------------------- Column sums
__global__ __launch_bounds__(256) void colsum_part_k(
    const float* __restrict__ attn, float* __restrict__ part)
{
    const int k  = blockIdx.x * 256 + threadIdx.x;   // 0..1023
    const int b  = blockIdx.y;
    const int rs = blockIdx.z;
    const int RC = Hh * Ss / RSPLIT;                 // 256 rows per split
    const float* base = attn + (long long)b * Hh * Ss * Ss
                             + (long long)rs * RC * Ss + k;
    float s = 0.f;
    #pragma unroll 8
    for (int r = 0; r < RC; r++) s += base[(long long)r * Ss];
    part[(rs * Bb + b) * Ss + k] = s;
}

__global__ __launch_bounds__(256) void colsum_fin_k(
    const float* __restrict__ part, float* __restrict__ amap)
{
    const int i = blockIdx.x * 256 + threadIdx.x;    // 0..2047
    float s = 0.f;
    #pragma unroll
    for (int rs = 0; rs < RSPLIT; rs++) s += part[rs * Bb * Ss + i];
    amap[i] += s;
}

// ---------------------------------------------------------------- misc
__global__ __launch_bounds__(256) void save_ctx_k(
    const float* __restrict__ x, float4* __restrict__ st, int layer)
{
    const int i  = blockIdx.x * 256 + threadIdx.x;   // over BS*D/4
    const int d4 = i & 255;
    const int bs = i >> 8;
    st[((long long)bs * DEPTH + layer) * 256 + d4] = ((const float4*)x)[i];
}

__global__ void zero_k(float* p, int n)
{
    int i = blockIdx.x * 256 + threadIdx.x;
    if (i < n) p[i] = 0.f;
}

// ---------------------------------------------------------------- launcher
extern "C" void kernel_launch(void* const* d_in, const int* in_sizes, int n_in,
                              void* d_out, int out_size)
{
    const float* token = (const float*)d_in[0];
    const float* Wq    = (const float*)d_in[1];
    const float* Wkv   = (const float*)d_in[2];
    const float* Wo    = (const float*)d_in[3];
    const float* b_o   = (const float*)d_in[4];
    const float* g1    = (const float*)d_in[5];
    const float* b1    = (const float*)d_in[6];
    const float* g3    = (const float*)d_in[7];
    const float* b3    = (const float*)d_in[8];
    const float* W1    = (const float*)d_in[9];
    const float* W2    = (const float*)d_in[10];
    const float* gout  = (const float*)d_in[11];
    const float* bout  = (const float*)d_in[12];
    float* out = (float*)d_out;

    float *x, *xn, *qkv, *wqkv, *attn, *y, *ff, *red, *part;
    cudaGetSymbolAddress((void**)&x,    g_x);
    cudaGetSymbolAddress((void**)&xn,   g_xn);
    cudaGetSymbolAddress((void**)&qkv,  g_qkv);
    cudaGetSymbolAddress((void**)&wqkv, g_wqkv);
    cudaGetSymbolAddress((void**)&attn, g_attn);
    cudaGetSymbolAddress((void**)&y,    g_y);
    cudaGetSymbolAddress((void**)&ff,   g_ff);
    cudaGetSymbolAddress((void**)&red,  g_red);
    cudaGetSymbolAddress((void**)&part, g_part);

    float* out_state = out + (size_t)BS * Dd;
    float* amap      = out_state + (size_t)BS * DEPTH * Dd;

    cudaMemcpyAsync(x, token, sizeof(float) * BS * Dd, cudaMemcpyDeviceToDevice, 0);
    zero_k<<<(BS + 255) / 256, 256>>>(amap, BS);
    pack_w<<<DEPTH * Dd * 3 * Dd / 4 / 256, 256>>>(
        (const float4*)Wq, (const float4*)Wkv, (float4*)wqkv);

    const float scale = rsqrtf((float)HD);
    const int D3 = 3 * Dd;
    const int NRED = BS * Dd / 4 / 256;

    for (int l = 0; l < DEPTH; l++) {
        // context snapshot
        save_ctx_k<<<BS * Dd / 4 / 256, 256>>>(x, (float4*)out_state, l);
        // LN1
        ln_k<<<BS, 256>>>(x, g1 + l * Dd, b1 + l * Dd, xn);
        // QKV = xn @ [Wq|Wkv]   (N=3072 -> 384 CTAs)
        gemm_tc<0, false><<<dim3(D3 / BN, BS / BM, 1), 256>>>(
            xn, wqkv + (size_t)l * Dd * D3, qkv, nullptr,
            Dd, Dd, D3, D3, 0, 0, 0, 0, 0, 0, 1, 1.f, 0);
        // scores = scale * Q @ K^T  (batched over b,h; causal tile-skip)
        gemm_tc<0, true><<<dim3(Ss / BN, Ss / BM, Bb * Hh), 256>>>(
            qkv, qkv + Dd, attn, nullptr,
            HD, D3, D3, Ss,
            (long long)Ss * D3, HD,
            (long long)Ss * D3, HD,
            (long long)Hh * Ss * Ss, (long long)Ss * Ss,
            Hh, scale, 1);
        // softmax rows
        softmax_k<<<Bb * Hh * Ss, 256>>>(attn);
        // attention-map column sums
        colsum_part_k<<<dim3(Ss / 256, Bb, RSPLIT), 256>>>(attn, part);
        colsum_fin_k<<<Bb * Ss / 256, 256>>>(part, amap);
        // y = attn @ V   (causal K-trim)
        gemm_tc<0, false><<<dim3(HD / BN, Ss / BM, Bb * Hh), 256>>>(
            attn, qkv + 2 * Dd, y, nullptr,
            Ss, Ss, D3, Dd,
            (long long)Hh * Ss * Ss, (long long)Ss * Ss,
            (long long)Ss * D3, HD,
            (long long)Ss * Dd, HD,
            Hh, 1.f, 2);
        // x += y @ Wo + b_o   (split-K=2 -> partials + reduce)
        gemm_tc<0, false><<<dim3(Dd / BN, BS / BM, 2), 256>>>(
            y, Wo + (size_t)l * Dd * Dd, red, nullptr,
            Dd / 2, Dd, Dd, Dd,
            0, Dd / 2, 0, (long long)(Dd / 2) * Dd,
            0, (long long)BS * Dd,
            2, 1.f, 0);
        reduce_add_k<2, true><<<NRED, 256>>>((const float4*)red, (float4*)x, b_o + l * Dd);
        // LN2
        ln_k<<<BS, 256>>>(x, g3 + l * Dd, b3 + l * Dd, xn);
        // ff = gelu(xn @ W1)
        gemm_tc<2, false><<<dim3(FF / BN, BS / BM, 1), 256>>>(
            xn, W1 + (size_t)l * Dd * FF, ff, nullptr,
            Dd, Dd, FF, FF, 0, 0, 0, 0, 0, 0, 1, 1.f, 0);
        // x += ff @ W2   (split-K=4 -> partials + reduce)
        gemm_tc<0, false><<<dim3(Dd / BN, BS / BM, 4), 256>>>(
            ff, W2 + (size_t)l * FF * Dd, red, nullptr,
            FF / 4, FF, Dd, Dd,
            0, FF / 4, 0, (long long)(FF / 4) * Dd,
            0, (long long)BS * Dd,
            4, 1.f, 0);
        reduce_add_k<4, false><<<NRED, 256>>>((const float4*)red, (float4*)x, nullptr);
    }
    // final LN -> x_out
    ln_k<<<BS, 256>>>(x, gout, bout, out);
}

// round 5
// speedup vs baseline: 2.6084x; 1.0316x over previous
#include <cuda_runtime.h>
#include <math.h>

// Problem constants
constexpr int Bb    = 2;
constexpr int Ss    = 1024;
constexpr int Dd    = 1024;
constexpr int Hh    = 8;
constexpr int HD    = 128;
constexpr int DEPTH = 8;
constexpr int FF    = 4096;
constexpr int BS    = Bb * Ss;      // 2048
constexpr int RSPLIT = 32;

// Scratch (device globals: allocation-free)
__device__ float g_x  [BS * Dd];
__device__ float g_xn [BS * Dd];
__device__ float g_qkv[(size_t)BS * 3 * Dd];            // q | k | v packed
__device__ float g_wqkv[(size_t)DEPTH * Dd * 3 * Dd];   // [Wq | Wkv] packed, 96MB
__device__ float g_attn[(size_t)Bb * Hh * Ss * Ss];     // 64 MB
__device__ float g_y  [BS * Dd];
__device__ float g_ff [(size_t)BS * FF];                // 32 MB
__device__ float g_red[(size_t)4 * BS * Dd];            // split-K partials, 32MB
__device__ float g_part[RSPLIT * Bb * Ss];

// ---------------------------------------------------------------- tf32 helpers
__device__ __forceinline__ unsigned f2tf32(float x) {
    unsigned r;
    asm("cvt.rna.tf32.f32 %0, %1;" : "=r"(r) : "f"(x));
    return r;
}
__device__ __forceinline__ float tf32f(float x) {
    return __uint_as_float(f2tf32(x));
}

__device__ __forceinline__ void mma_tf32(float* c, const unsigned* a, const unsigned* b) {
    asm volatile(
        "mma.sync.aligned.m16n8k8.row.col.f32.tf32.tf32.f32 "
        "{%0,%1,%2,%3}, {%4,%5,%6,%7}, {%8,%9}, {%0,%1,%2,%3};"
        : "+f"(c[0]), "+f"(c[1]), "+f"(c[2]), "+f"(c[3])
        : "r"(a[0]), "r"(a[1]), "r"(a[2]), "r"(a[3]), "r"(b[0]), "r"(b[1]));
}

__device__ __forceinline__ void ldsm4(unsigned& r0, unsigned& r1, unsigned& r2,
                                      unsigned& r3, unsigned addr) {
    asm volatile("ldmatrix.sync.aligned.m8n8.x4.shared.b16 {%0,%1,%2,%3}, [%4];"
                 : "=r"(r0), "=r"(r1), "=r"(r2), "=r"(r3) : "r"(addr));
}

// ---------------------------------------------------------------- tensor-core GEMM
// C[M,N] = epilogue(alpha * A[M,K] @ B[K,N])
// TRANSB: B stored [N,K] row-major, i.e. C = A @ B^T
// EPI: 0 = store, 1 = C += acc + bias[col], 2 = store gelu(acc), 3 = C += acc
// causal: 0 none, 1 = skip tiles fully above diagonal (scores), 2 = K-trim (A·V)
// 128x128 CTA tile, 4 warps of 64x64. BK=16.
#define BM 128
#define BN 128
#define BK 16
#define ALEN 20     // As / Bs(trans) row length: 80B rows, 16B-aligned, conflict-free ldsm
#define BLENN 136   // Bs(non-trans) [k][n] row length: t*136+g hits all 32 banks
#define BSMAX 2560  // max of 128*20, 16*136

template<int EPI, bool TRANSB>
__global__ __launch_bounds__(128, 2) void gemm_tc(
    const float* __restrict__ A, const float* __restrict__ Bg,
    float* __restrict__ C, const float* __restrict__ bias,
    int K, int lda, int ldb, int ldc,
    long long sAo, long long sAi, long long sBo, long long sBi,
    long long sCo, long long sCi, int zdiv,
    float alpha, int causal)
{
    const int bm = blockIdx.y * BM;
    const int bn = blockIdx.x * BN;
    if (causal == 1 && bn >= bm + BM) return;     // fully above causal diagonal
    const int Keff = (causal == 2) ? min(K, bm + BM) : K;

    const int z  = blockIdx.z;
    const int zo = z / zdiv;
    const int zi = z - zo * zdiv;
    A  += zo * sAo + zi * sAi;
    Bg += zo * sBo + zi * sBi;
    C  += zo * sCo + zi * sCi;

    __shared__ __align__(16) float As[2][BM * ALEN];   // [m][k]
    __shared__ __align__(16) float Bs[2][BSMAX];       // trans: [n][k] | ntrans: [k][n]

    const int tid  = threadIdx.x;
    const int lane = tid & 31;
    const int warp = tid >> 5;              // 0..3
    const int wm   = (warp & 1) * 64;       // warp tile 64(M) x 64(N)
    const int wn   = (warp >> 1) * 64;
    const int g    = lane >> 2;             // 0..7
    const int t    = lane & 3;              // 0..3

    // ldmatrix per-lane offsets
    const int lp = lane >> 3;
    const int lr = lane & 7;
    const int aRowOff = (lp & 1) * 8 + lr;
    const int aColOff = (lp >> 1) * 4;
    const int bRowOff = (lp >> 1) * 8 + lr;   // for [n][k] b-frag ldsm
    const int bColOff = (lp & 1) * 4;
    const unsigned asb0 = (unsigned)__cvta_generic_to_shared(&As[0][0]);
    const unsigned asb1 = (unsigned)__cvta_generic_to_shared(&As[1][0]);
    const unsigned bsb0 = (unsigned)__cvta_generic_to_shared(&Bs[0][0]);
    const unsigned bsb1 = (unsigned)__cvta_generic_to_shared(&Bs[1][0]);

    float acc[4][8][4];
    #pragma unroll
    for (int i = 0; i < 4; i++)
        #pragma unroll
        for (int j = 0; j < 8; j++)
            #pragma unroll
            for (int r = 0; r < 4; r++) acc[i][j][r] = 0.f;

    // global-load mappings (128 threads)
    const int arow = tid >> 2;              // 0..31 (+32h)
    const int ac4  = (tid & 3) * 4;         // k offset
    const int bkr  = tid >> 5;              // 0..3 (+4h)   (non-trans)
    const int bnc  = (tid & 31) * 4;        // n offset     (non-trans)

    float4 ra[4], rb[4];

    auto loadG = [&](int k0) {
        #pragma unroll
        for (int h = 0; h < 4; h++)
            ra[h] = *(const float4*)&A[(long long)(bm + arow + 32 * h) * lda + k0 + ac4];
        if (!TRANSB) {
            #pragma unroll
            for (int h = 0; h < 4; h++)
                rb[h] = *(const float4*)&Bg[(long long)(k0 + bkr + 4 * h) * ldb + bn + bnc];
        } else {
            #pragma unroll
            for (int h = 0; h < 4; h++)
                rb[h] = *(const float4*)&Bg[(long long)(bn + arow + 32 * h) * ldb + k0 + ac4];
        }
    };
    auto storeS = [&](int p) {
        #pragma unroll
        for (int h = 0; h < 4; h++) {
            float4 v = make_float4(tf32f(ra[h].x), tf32f(ra[h].y),
                                   tf32f(ra[h].z), tf32f(ra[h].w));
            *(float4*)&As[p][(arow + 32 * h) * ALEN + ac4] = v;
        }
        if (!TRANSB) {
            #pragma unroll
            for (int h = 0; h < 4; h++) {
                float4 v = make_float4(tf32f(rb[h].x), tf32f(rb[h].y),
                                       tf32f(rb[h].z), tf32f(rb[h].w));
                *(float4*)&Bs[p][(bkr + 4 * h) * BLENN + bnc] = v;
            }
        } else {
            #pragma unroll
            for (int h = 0; h < 4; h++) {
                float4 v = make_float4(tf32f(rb[h].x), tf32f(rb[h].y),
                                       tf32f(rb[h].z), tf32f(rb[h].w));
                *(float4*)&Bs[p][(arow + 32 * h) * ALEN + ac4] = v;
            }
        }
    };
    auto compute = [&](int p) {
        const unsigned abase = (p ? asb1 : asb0)
                             + ((wm + aRowOff) * ALEN + aColOff) * 4;
        const unsigned bbase = (p ? bsb1 : bsb0)
                             + ((wn + bRowOff) * ALEN + bColOff) * 4;   // trans only
        #pragma unroll
        for (int ks = 0; ks < 2; ks++) {
            const int kk = ks * 8;
            unsigned af[4][4], bf[8][2];
            #pragma unroll
            for (int i = 0; i < 4; i++)
                ldsm4(af[i][0], af[i][1], af[i][2], af[i][3],
                      abase + (unsigned)((i * 16 * ALEN + kk) * 4));
            if (TRANSB) {
                #pragma unroll
                for (int jp = 0; jp < 4; jp++)
                    ldsm4(bf[2 * jp][0], bf[2 * jp][1], bf[2 * jp + 1][0], bf[2 * jp + 1][1],
                          bbase + (unsigned)((jp * 16 * ALEN + kk) * 4));
            } else {
                #pragma unroll
                for (int j = 0; j < 8; j++) {
                    int c0 = wn + j * 8 + g;
                    bf[j][0] = __float_as_uint(Bs[p][(kk + t    ) * BLENN + c0]);
                    bf[j][1] = __float_as_uint(Bs[p][(kk + t + 4) * BLENN + c0]);
                }
            }
            #pragma unroll
            for (int i = 0; i < 4; i++)
                #pragma unroll
                for (int j = 0; j < 8; j++)
                    mma_tf32(acc[i][j], af[i], bf[j]);
        }
    };

    const int nk = Keff / BK;
    loadG(0);
    storeS(0);
    __syncthreads();
    for (int kt = 0; kt < nk; kt++) {
        const int p = kt & 1;
        if (kt + 1 < nk) loadG((kt + 1) * BK);
        compute(p);
        if (kt + 1 < nk) {
            storeS(p ^ 1);
            __syncthreads();
        }
    }

    // Epilogue
    #pragma unroll
    for (int i = 0; i < 4; i++) {
        #pragma unroll
        for (int j = 0; j < 8; j++) {
            const long long row = bm + wm + i * 16 + g;
            const int       col = bn + wn + j * 8 + 2 * t;
            float2 v0 = make_float2(acc[i][j][0] * alpha, acc[i][j][1] * alpha);
            float2 v1 = make_float2(acc[i][j][2] * alpha, acc[i][j][3] * alpha);
            float* cp0 = &C[row * (long long)ldc + col];
            float* cp1 = &C[(row + 8) * (long long)ldc + col];
            if (EPI == 0) {
                *(float2*)cp0 = v0;
                *(float2*)cp1 = v1;
            } else if (EPI == 1) {
                float2 bb = *(const float2*)&bias[col];
                float2 o0 = *(const float2*)cp0;
                float2 o1 = *(const float2*)cp1;
                o0.x += v0.x + bb.x; o0.y += v0.y + bb.y;
                o1.x += v1.x + bb.x; o1.y += v1.y + bb.y;
                *(float2*)cp0 = o0;
                *(float2*)cp1 = o1;
            } else if (EPI == 2) {
                const float c = 0.70710678118654752f;
                v0.x = 0.5f * v0.x * erfcf(-v0.x * c);
                v0.y = 0.5f * v0.y * erfcf(-v0.y * c);
                v1.x = 0.5f * v1.x * erfcf(-v1.x * c);
                v1.y = 0.5f * v1.y * erfcf(-v1.y * c);
                *(float2*)cp0 = v0;
                *(float2*)cp1 = v1;
            } else {
                float2 o0 = *(const float2*)cp0;
                float2 o1 = *(const float2*)cp1;
                o0.x += v0.x; o0.y += v0.y;
                o1.x += v1.x; o1.y += v1.y;
                *(float2*)cp0 = o0;
                *(float2*)cp1 = o1;
            }
        }
    }
}

// ---------------------------------------------------------------- split-K reduce
template<int P, bool BIAS>
__global__ __launch_bounds__(256) void reduce_add_k(
    const float4* __restrict__ part, float4* __restrict__ x,
    const float* __restrict__ bias)
{
    const int i = blockIdx.x * 256 + threadIdx.x;    // over BS*Dd/4
    constexpr int N4 = BS * Dd / 4;
    float4 s = part[i];
    #pragma unroll
    for (int p = 1; p < P; p++) {
        float4 v = part[(size_t)p * N4 + i];
        s.x += v.x; s.y += v.y; s.z += v.z; s.w += v.w;
    }
    if (BIAS) {
        float4 bb = ((const float4*)bias)[i & (Dd / 4 - 1)];
        s.x += bb.x; s.y += bb.y; s.z += bb.z; s.w += bb.w;
    }
    float4 o = x[i];
    o.x += s.x; o.y += s.y; o.z += s.z; o.w += s.w;
    x[i] = o;
}

// ---------------------------------------------------------------- weight pack
__global__ __launch_bounds__(256) void pack_w(
    const float4* __restrict__ Wq, const float4* __restrict__ Wkv,
    float4* __restrict__ wqkv)
{
    const long long i = (long long)blockIdx.x * 256 + threadIdx.x;   // DEPTH*D*3D/4
    const int C4 = 3 * Dd / 4;                                       // 768
    const long long row = i / C4;                                    // l*D + d
    const int c4 = (int)(i - row * C4);
    float4 v = (c4 < Dd / 4) ? Wq[row * (Dd / 4) + c4]
                             : Wkv[row * (2 * Dd / 4) + (c4 - Dd / 4)];
    wqkv[i] = v;
}

// ---------------------------------------------------------------- LayerNorm
__global__ __launch_bounds__(256) void ln_k(
    const float* __restrict__ x, const float* __restrict__ g,
    const float* __restrict__ b, float* __restrict__ out)
{
    __shared__ float sm0[8], sm1[8];
    const int row = blockIdx.x, tid = threadIdx.x;
    float4 v = ((const float4*)(x + (long long)row * Dd))[tid];
    float s  = v.x + v.y + v.z + v.w;
    float s2 = v.x * v.x + v.y * v.y + v.z * v.z + v.w * v.w;
    #pragma unroll
    for (int o = 16; o > 0; o >>= 1) {
        s  += __shfl_xor_sync(0xffffffffu, s,  o);
        s2 += __shfl_xor_sync(0xffffffffu, s2, o);
    }
    if ((tid & 31) == 0) { sm0[tid >> 5] = s; sm1[tid >> 5] = s2; }
    __syncthreads();
    if (tid < 32) {
        s  = (tid < 8) ? sm0[tid] : 0.f;
        s2 = (tid < 8) ? sm1[tid] : 0.f;
        #pragma unroll
        for (int o = 4; o > 0; o >>= 1) {
            s  += __shfl_xor_sync(0xffffffffu, s,  o);
            s2 += __shfl_xor_sync(0xffffffffu, s2, o);
        }
        if (tid == 0) { sm0[0] = s; sm1[0] = s2; }
    }
    __syncthreads();
    const float mean = sm0[0] * (1.f / Dd);
    const float var  = sm1[0] * (1.f / Dd) - mean * mean;
    const float rstd = rsqrtf(var + 1e-5f);
    float4 gg = ((const float4*)g)[tid];
    float4 bb = ((const float4*)b)[tid];
    float4 o;
    o.x = (v.x - mean) * rstd * gg.x + bb.x;
    o.y = (v.y - mean) * rstd * gg.y + bb.y;
    o.z = (v.z - mean) * rstd * gg.z + bb.z;
    o.w = (v.w - mean) * rstd * gg.w + bb.w;
    ((float4*)(out + (long long)row * Dd))[tid] = o;
}

// ---------------------------------------------------------------- Softmax (causal row)
__global__ __launch_bounds__(256) void softmax_k(float* __restrict__ attn)
{
    __shared__ float sm[8];
    const int row = blockIdx.x;
    const int q   = row & (Ss - 1);
    float* p = attn + (long long)row * Ss;
    const int tid = threadIdx.x;
    const int k0  = tid * 4;
    float4 v = ((const float4*)p)[tid];

    float m = -1e30f;
    if (k0 + 0 <= q) m = fmaxf(m, v.x);
    if (k0 + 1 <= q) m = fmaxf(m, v.y);
    if (k0 + 2 <= q) m = fmaxf(m, v.z);
    if (k0 + 3 <= q) m = fmaxf(m, v.w);
    #pragma unroll
    for (int o = 16; o > 0; o >>= 1) m = fmaxf(m, __shfl_xor_sync(0xffffffffu, m, o));
    if ((tid & 31) == 0) sm[tid >> 5] = m;
    __syncthreads();
    if (tid < 32) {
        float t = (tid < 8) ? sm[tid] : -1e30f;
        #pragma unroll
        for (int o = 4; o > 0; o >>= 1) t = fmaxf(t, __shfl_xor_sync(0xffffffffu, t, o));
        if (tid == 0) sm[0] = t;
    }
    __syncthreads();
    m = sm[0];
    __syncthreads();

    float4 e;
    e.x = (k0 + 0 <= q) ? __expf(v.x - m) : 0.f;
    e.y = (k0 + 1 <= q) ? __expf(v.y - m) : 0.f;
    e.z = (k0 + 2 <= q) ? __expf(v.z - m) : 0.f;
    e.w = (k0 + 3 <= q) ? __expf(v.w - m) : 0.f;
    float s = e.x + e.y + e.z + e.w;
    #pragma unroll
    for (int o = 16; o > 0; o >>= 1) s += __shfl_xor_sync(0xffffffffu, s, o);
    if ((tid & 31) == 0) sm[tid >> 5] = s;
    __syncthreads();
    if (tid < 32) {
        float t = (tid < 8) ? sm[tid] : 0.f;
        #pragma unroll
        for (int o = 4; o > 0; o >>= 1) t += __shfl_xor_sync(0xffffffffu, t, o);
        if (tid == 0) sm[0] = t;
    }
    __syncthreads();
    const float inv = 1.f / sm[0];
    e.x *= inv; e.y *= inv; e.z *= inv; e.w *= inv;
    ((float4*)p)[tid] = e;
}

// ---------------------------------------------------------------- Column sums
__global__ __launch_bounds__(256) void colsum_part_k(
    const float* __restrict__ attn, float* __restrict__ part)
{
    const int k  = blockIdx.x * 256 + threadIdx.x;   // 0..1023
    const int b  = blockIdx.y;
    const int rs = blockIdx.z;
    const int RC = Hh * Ss / RSPLIT;                 // 256 rows per split
    const float* base = attn + (long long)b * Hh * Ss * Ss
                             + (long long)rs * RC * Ss + k;
    float s = 0.f;
    #pragma unroll 8
    for (int r = 0; r < RC; r++) s += base[(long long)r * Ss];
    part[(rs * Bb + b) * Ss + k] = s;
}

__global__ __launch_bounds__(256) void colsum_fin_k(
    const float* __restrict__ part, float* __restrict__ amap)
{
    const int i = blockIdx.x * 256 + threadIdx.x;    // 0..2047
    float s = 0.f;
    #pragma unroll
    for (int rs = 0; rs < RSPLIT; rs++) s += part[rs * Bb * Ss + i];
    amap[i] += s;
}

// ---------------------------------------------------------------- misc
__global__ __launch_bounds__(256) void save_ctx_k(
    const float* __restrict__ x, float4* __restrict__ st, int layer)
{
    const int i  = blockIdx.x * 256 + threadIdx.x;   // over BS*D/4
    const int d4 = i & 255;
    const int bs = i >> 8;
    st[((long long)bs * DEPTH + layer) * 256 + d4] = ((const float4*)x)[i];
}

__global__ void zero_k(float* p, int n)
{
    int i = blockIdx.x * 256 + threadIdx.x;
    if (i < n) p[i] = 0.f;
}

// ---------------------------------------------------------------- launcher
extern "C" void kernel_launch(void* const* d_in, const int* in_sizes, int n_in,
                              void* d_out, int out_size)
{
    const float* token = (const float*)d_in[0];
    const float* Wq    = (const float*)d_in[1];
    const float* Wkv   = (const float*)d_in[2];
    const float* Wo    = (const float*)d_in[3];
    const float* b_o   = (const float*)d_in[4];
    const float* g1    = (const float*)d_in[5];
    const float* b1    = (const float*)d_in[6];
    const float* g3    = (const float*)d_in[7];
    const float* b3    = (const float*)d_in[8];
    const float* W1    = (const float*)d_in[9];
    const float* W2    = (const float*)d_in[10];
    const float* gout  = (const float*)d_in[11];
    const float* bout  = (const float*)d_in[12];
    float* out = (float*)d_out;

    float *x, *xn, *qkv, *wqkv, *attn, *y, *ff, *red, *part;
    cudaGetSymbolAddress((void**)&x,    g_x);
    cudaGetSymbolAddress((void**)&xn,   g_xn);
    cudaGetSymbolAddress((void**)&qkv,  g_qkv);
    cudaGetSymbolAddress((void**)&wqkv, g_wqkv);
    cudaGetSymbolAddress((void**)&attn, g_attn);
    cudaGetSymbolAddress((void**)&y,    g_y);
    cudaGetSymbolAddress((void**)&ff,   g_ff);
    cudaGetSymbolAddress((void**)&red,  g_red);
    cudaGetSymbolAddress((void**)&part, g_part);

    float* out_state = out + (size_t)BS * Dd;
    float* amap      = out_state + (size_t)BS * DEPTH * Dd;

    cudaMemcpyAsync(x, token, sizeof(float) * BS * Dd, cudaMemcpyDeviceToDevice, 0);
    zero_k<<<(BS + 255) / 256, 256>>>(amap, BS);
    pack_w<<<DEPTH * Dd * 3 * Dd / 4 / 256, 256>>>(
        (const float4*)Wq, (const float4*)Wkv, (float4*)wqkv);

    const float scale = rsqrtf((float)HD);
    const int D3 = 3 * Dd;
    const int NRED = BS * Dd / 4 / 256;

    for (int l = 0; l < DEPTH; l++) {
        // context snapshot
        save_ctx_k<<<BS * Dd / 4 / 256, 256>>>(x, (float4*)out_state, l);
        // LN1
        ln_k<<<BS, 256>>>(x, g1 + l * Dd, b1 + l * Dd, xn);
        // QKV = xn @ [Wq|Wkv]   (N=3072 -> 384 CTAs)
        gemm_tc<0, false><<<dim3(D3 / BN, BS / BM, 1), 128>>>(
            xn, wqkv + (size_t)l * Dd * D3, qkv, nullptr,
            Dd, Dd, D3, D3, 0, 0, 0, 0, 0, 0, 1, 1.f, 0);
        // scores = scale * Q @ K^T  (batched over b,h; causal tile-skip)
        gemm_tc<0, true><<<dim3(Ss / BN, Ss / BM, Bb * Hh), 128>>>(
            qkv, qkv + Dd, attn, nullptr,
            HD, D3, D3, Ss,
            (long long)Ss * D3, HD,
            (long long)Ss * D3, HD,
            (long long)Hh * Ss * Ss, (long long)Ss * Ss,
            Hh, scale, 1);
        // softmax rows
        softmax_k<<<Bb * Hh * Ss, 256>>>(attn);
        // attention-map column sums
        colsum_part_k<<<dim3(Ss / 256, Bb, RSPLIT), 256>>>(attn, part);
        colsum_fin_k<<<Bb * Ss / 256, 256>>>(part, amap);
        // y = attn @ V   (causal K-trim)
        gemm_tc<0, false><<<dim3(HD / BN, Ss / BM, Bb * Hh), 128>>>(
            attn, qkv + 2 * Dd, y, nullptr,
            Ss, Ss, D3, Dd,
            (long long)Hh * Ss * Ss, (long long)Ss * Ss,
            (long long)Ss * D3, HD,
            (long long)Ss * Dd, HD,
            Hh, 1.f, 2);
        // x += y @ Wo + b_o   (split-K=2 -> partials + reduce)
        gemm_tc<0, false><<<dim3(Dd / BN, BS / BM, 2), 128>>>(
            y, Wo + (size_t)l * Dd * Dd, red, nullptr,
            Dd / 2, Dd, Dd, Dd,
            0, Dd / 2, 0, (long long)(Dd / 2) * Dd,
            0, (long long)BS * Dd,
            2, 1.f, 0);
        reduce_add_k<2, true><<<NRED, 256>>>((const float4*)red, (float4*)x, b_o + l * Dd);
        // LN2
        ln_k<<<BS, 256>>>(x, g3 + l * Dd, b3 + l * Dd, xn);
        // ff = gelu(xn @ W1)
        gemm_tc<2, false><<<dim3(FF / BN, BS / BM, 1), 128>>>(
            xn, W1 + (size_t)l * Dd * FF, ff, nullptr,
            Dd, Dd, FF, FF, 0, 0, 0, 0, 0, 0, 1, 1.f, 0);
        // x += ff @ W2   (split-K=4 -> partials + reduce)
        gemm_tc<0, false><<<dim3(Dd / BN, BS / BM, 4), 128>>>(
            ff, W2 + (size_t)l * FF * Dd, red, nullptr,
            FF / 4, FF, Dd, Dd,
            0, FF / 4, 0, (long long)(FF / 4) * Dd,
            0, (long long)BS * Dd,
            4, 1.f, 0);
        reduce_add_k<4, false><<<NRED, 256>>>((const float4*)red, (float4*)x, nullptr);
    }
    // final LN -> x_out
    ln_k<<<BS, 256>>>(x, gout, bout, out);
}

// round 6
// speedup vs baseline: 3.2261x; 1.2368x over previous
#include <cuda_runtime.h>
#include <math.h>

// Problem constants
constexpr int Bb    = 2;
constexpr int Ss    = 1024;
constexpr int Dd    = 1024;
constexpr int Hh    = 8;
constexpr int HD    = 128;
constexpr int DEPTH = 8;
constexpr int FF    = 4096;
constexpr int BS    = Bb * Ss;      // 2048
constexpr int RSPLIT = 32;

// Scratch (device globals: allocation-free)
__device__ float g_x  [BS * Dd];
__device__ float g_xn [BS * Dd];
__device__ float g_qkv[(size_t)BS * 3 * Dd];            // q | k | v packed
__device__ float g_wqkv[(size_t)DEPTH * Dd * 3 * Dd];   // [Wq | Wkv] packed+cvt, 96MB
__device__ float g_woc [(size_t)DEPTH * Dd * Dd];       // Wo  cvt, 32MB
__device__ float g_w1c [(size_t)DEPTH * Dd * FF];       // W1  cvt, 128MB
__device__ float g_w2c [(size_t)DEPTH * FF * Dd];       // W2  cvt, 128MB
__device__ float g_attn[(size_t)Bb * Hh * Ss * Ss];     // 64 MB
__device__ float g_y  [BS * Dd];
__device__ float g_ff [(size_t)BS * FF];                // 32 MB
__device__ float g_red[(size_t)4 * BS * Dd];            // split-K partials, 32MB
__device__ float g_part[RSPLIT * Bb * Ss];

// ---------------------------------------------------------------- tf32 helpers
__device__ __forceinline__ unsigned f2tf32(float x) {
    unsigned r;
    asm("cvt.rna.tf32.f32 %0, %1;" : "=r"(r) : "f"(x));
    return r;
}
__device__ __forceinline__ float tf32f(float x) {
    return __uint_as_float(f2tf32(x));
}

__device__ __forceinline__ void mma_tf32(float* c, const unsigned* a, const unsigned* b) {
    asm volatile(
        "mma.sync.aligned.m16n8k8.row.col.f32.tf32.tf32.f32 "
        "{%0,%1,%2,%3}, {%4,%5,%6,%7}, {%8,%9}, {%0,%1,%2,%3};"
        : "+f"(c[0]), "+f"(c[1]), "+f"(c[2]), "+f"(c[3])
        : "r"(a[0]), "r"(a[1]), "r"(a[2]), "r"(a[3]), "r"(b[0]), "r"(b[1]));
}

__device__ __forceinline__ void ldsm4(unsigned& r0, unsigned& r1, unsigned& r2,
                                      unsigned& r3, unsigned addr) {
    asm volatile("ldmatrix.sync.aligned.m8n8.x4.shared.b16 {%0,%1,%2,%3}, [%4];"
                 : "=r"(r0), "=r"(r1), "=r"(r2), "=r"(r3) : "r"(addr));
}

__device__ __forceinline__ void cp_async16(unsigned saddr, const void* gptr) {
    asm volatile("cp.async.cg.shared.global [%0], [%1], 16;"
                 :: "r"(saddr), "l"(gptr));
}
#define CP_COMMIT() asm volatile("cp.async.commit_group;")
#define CP_WAIT2()  asm volatile("cp.async.wait_group 2;")

// ---------------------------------------------------------------- tensor-core GEMM
// C[M,N] = epilogue(alpha * A[M,K] @ B[K,N]);  all operands pre-truncated to tf32.
// TRANSB: B stored [N,K] row-major, i.e. C = A @ B^T
// EPI: 0 = store, 2 = store gelu(acc)
// CVT: rna-truncate stored values (outputs that feed later GEMMs)
// causal: 0 none, 1 = skip tiles above diagonal (scores), 2 = K-trim (A·V)
#define BM 128
#define BN 128
#define BK 16
#define ALEN 20       // 80B rows: 16B-aligned, conflict-free ldmatrix
#define BLENN 136     // [k][n] row length: t*136+g hits all 32 banks
#define BSMAX 2560
#define STAGES 4
constexpr int A_STAGE = BM * ALEN;                       // 2560 floats
constexpr int B_STAGE = BSMAX;                           // 2560 floats
constexpr int GEMM_SMEM = STAGES * (A_STAGE + B_STAGE) * 4;  // 81920 B

template<int EPI, bool TRANSB, bool CVT>
__global__ __launch_bounds__(128, 2) void gemm_tc(
    const float* __restrict__ A, const float* __restrict__ Bg,
    float* __restrict__ C,
    int K, int lda, int ldb, int ldc,
    long long sAo, long long sAi, long long sBo, long long sBi,
    long long sCo, long long sCi, int zdiv,
    float alpha, int causal)
{
    const int bm = blockIdx.y * BM;
    const int bn = blockIdx.x * BN;
    if (causal == 1 && bn >= bm + BM) return;
    const int Keff = (causal == 2) ? min(K, bm + BM) : K;

    const int z  = blockIdx.z;
    const int zo = z / zdiv;
    const int zi = z - zo * zdiv;
    A  += zo * sAo + zi * sAi;
    Bg += zo * sBo + zi * sBi;
    C  += zo * sCo + zi * sCi;

    extern __shared__ float smem[];
    float* AsBase = smem;                        // [STAGES][A_STAGE]  [m][k]
    float* BsBase = smem + STAGES * A_STAGE;     // [STAGES][B_STAGE]  trans:[n][k] else [k][n]

    const int tid  = threadIdx.x;
    const int lane = tid & 31;
    const int warp = tid >> 5;              // 0..3
    const int wm   = (warp & 1) * 64;       // warp tile 64(M) x 64(N)
    const int wn   = (warp >> 1) * 64;
    const int g    = lane >> 2;             // 0..7
    const int t    = lane & 3;              // 0..3

    // ldmatrix per-lane offsets
    const int lp = lane >> 3;
    const int lr = lane & 7;
    const int aRowOff = (lp & 1) * 8 + lr;
    const int aColOff = (lp >> 1) * 4;
    const int bRowOff = (lp >> 1) * 8 + lr;   // [n][k] b-frag ldsm (trans)
    const int bColOff = (lp & 1) * 4;
    const unsigned asb = (unsigned)__cvta_generic_to_shared(AsBase);
    const unsigned bsb = (unsigned)__cvta_generic_to_shared(BsBase);

    float acc[4][8][4];
    #pragma unroll
    for (int i = 0; i < 4; i++)
        #pragma unroll
        for (int j = 0; j < 8; j++)
            #pragma unroll
            for (int r = 0; r < 4; r++) acc[i][j][r] = 0.f;

    // global->smem cp.async mappings (128 threads, 16B each)
    const int arow = tid >> 2;              // 0..31 (+32h)
    const int ac4  = (tid & 3) * 4;         // k offset
    const int bkr  = tid >> 5;              // 0..3 (+4h)  (non-trans)
    const int bnc  = (tid & 31) * 4;        // n offset    (non-trans)

    auto issueStage = [&](int s, int k0) {
        const unsigned aB = asb + (unsigned)(s * A_STAGE * 4);
        #pragma unroll
        for (int h = 0; h < 4; h++)
            cp_async16(aB + (unsigned)(((arow + 32 * h) * ALEN + ac4) * 4),
                       &A[(long long)(bm + arow + 32 * h) * lda + k0 + ac4]);
        const unsigned bB = bsb + (unsigned)(s * B_STAGE * 4);
        if (!TRANSB) {
            #pragma unroll
            for (int h = 0; h < 4; h++)
                cp_async16(bB + (unsigned)(((bkr + 4 * h) * BLENN + bnc) * 4),
                           &Bg[(long long)(k0 + bkr + 4 * h) * ldb + bn + bnc]);
        } else {
            #pragma unroll
            for (int h = 0; h < 4; h++)
                cp_async16(bB + (unsigned)(((arow + 32 * h) * ALEN + ac4) * 4),
                           &Bg[(long long)(bn + arow + 32 * h) * ldb + k0 + ac4]);
        }
    };

    auto compute = [&](int p) {
        const float* Bsp = BsBase + p * B_STAGE;
        const unsigned abase = asb + (unsigned)(p * A_STAGE * 4)
                             + (unsigned)(((wm + aRowOff) * ALEN + aColOff) * 4);
        const unsigned bbase = bsb + (unsigned)(p * B_STAGE * 4)
                             + (unsigned)(((wn + bRowOff) * ALEN + bColOff) * 4);
        #pragma unroll
        for (int ks = 0; ks < 2; ks++) {
            const int kk = ks * 8;
            unsigned af[4][4], bf[8][2];
            #pragma unroll
            for (int i = 0; i < 4; i++)
                ldsm4(af[i][0], af[i][1], af[i][2], af[i][3],
                      abase + (unsigned)((i * 16 * ALEN + kk) * 4));
            if (TRANSB) {
                #pragma unroll
                for (int jp = 0; jp < 4; jp++)
                    ldsm4(bf[2 * jp][0], bf[2 * jp][1], bf[2 * jp + 1][0], bf[2 * jp + 1][1],
                          bbase + (unsigned)((jp * 16 * ALEN + kk) * 4));
            } else {
                #pragma unroll
                for (int j = 0; j < 8; j++) {
                    int c0 = wn + j * 8 + g;
                    bf[j][0] = __float_as_uint(Bsp[(kk + t    ) * BLENN + c0]);
                    bf[j][1] = __float_as_uint(Bsp[(kk + t + 4) * BLENN + c0]);
                }
            }
            #pragma unroll
            for (int i = 0; i < 4; i++)
                #pragma unroll
                for (int j = 0; j < 8; j++)
                    mma_tf32(acc[i][j], af[i], bf[j]);
        }
    };

    const int nk = Keff / BK;               // nk >= 8 for all shapes here
    #pragma unroll
    for (int s = 0; s < STAGES - 1; s++) {  // prefetch 3 tiles
        issueStage(s, s * BK);
        CP_COMMIT();
    }
    for (int kt = 0; kt < nk; kt++) {
        CP_WAIT2();                          // tile kt landed
        __syncthreads();
        compute(kt % STAGES);
        if (kt + STAGES - 1 < nk)
            issueStage((kt + STAGES - 1) % STAGES, (kt + STAGES - 1) * BK);
        CP_COMMIT();                         // always commit (may be empty)
    }

    // Epilogue
    #pragma unroll
    for (int i = 0; i < 4; i++) {
        #pragma unroll
        for (int j = 0; j < 8; j++) {
            const long long row = bm + wm + i * 16 + g;
            const int       col = bn + wn + j * 8 + 2 * t;
            float2 v0 = make_float2(acc[i][j][0] * alpha, acc[i][j][1] * alpha);
            float2 v1 = make_float2(acc[i][j][2] * alpha, acc[i][j][3] * alpha);
            float* cp0 = &C[row * (long long)ldc + col];
            float* cp1 = &C[(row + 8) * (long long)ldc + col];
            if (EPI == 2) {
                const float c = 0.70710678118654752f;
                v0.x = 0.5f * v0.x * erfcf(-v0.x * c);
                v0.y = 0.5f * v0.y * erfcf(-v0.y * c);
                v1.x = 0.5f * v1.x * erfcf(-v1.x * c);
                v1.y = 0.5f * v1.y * erfcf(-v1.y * c);
            }
            if (CVT) {
                v0.x = tf32f(v0.x); v0.y = tf32f(v0.y);
                v1.x = tf32f(v1.x); v1.y = tf32f(v1.y);
            }
            *(float2*)cp0 = v0;
            *(float2*)cp1 = v1;
        }
    }
}

// ---------------------------------------------------------------- split-K reduce
template<int P, bool BIAS>
__global__ __launch_bounds__(256) void reduce_add_k(
    const float4* __restrict__ part, float4* __restrict__ x,
    const float* __restrict__ bias)
{
    const int i = blockIdx.x * 256 + threadIdx.x;    // over BS*Dd/4
    constexpr int N4 = BS * Dd / 4;
    float4 s = part[i];
    #pragma unroll
    for (int p = 1; p < P; p++) {
        float4 v = part[(size_t)p * N4 + i];
        s.x += v.x; s.y += v.y; s.z += v.z; s.w += v.w;
    }
    if (BIAS) {
        float4 bb = ((const float4*)bias)[i & (Dd / 4 - 1)];
        s.x += bb.x; s.y += bb.y; s.z += bb.z; s.w += bb.w;
    }
    float4 o = x[i];
    o.x += s.x; o.y += s.y; o.z += s.z; o.w += s.w;
    x[i] = o;
}

// ---------------------------------------------------------------- weight pack / cvt
__global__ __launch_bounds__(256) void pack_w(
    const float4* __restrict__ Wq, const float4* __restrict__ Wkv,
    float4* __restrict__ wqkv)
{
    const long long i = (long long)blockIdx.x * 256 + threadIdx.x;   // DEPTH*D*3D/4
    const int C4 = 3 * Dd / 4;                                       // 768
    const long long row = i / C4;
    const int c4 = (int)(i - row * C4);
    float4 v = (c4 < Dd / 4) ? Wq[row * (Dd / 4) + c4]
                             : Wkv[row * (2 * Dd / 4) + (c4 - Dd / 4)];
    v.x = tf32f(v.x); v.y = tf32f(v.y); v.z = tf32f(v.z); v.w = tf32f(v.w);
    wqkv[i] = v;
}

__global__ __launch_bounds__(256) void cvt_copy_k(
    const float4* __restrict__ src, float4* __restrict__ dst)
{
    const long long i = (long long)blockIdx.x * 256 + threadIdx.x;
    float4 v = src[i];
    v.x = tf32f(v.x); v.y = tf32f(v.y); v.z = tf32f(v.z); v.w = tf32f(v.w);
    dst[i] = v;
}

// ---------------------------------------------------------------- LayerNorm
__global__ __launch_bounds__(256) void ln_k(
    const float* __restrict__ x, const float* __restrict__ g,
    const float* __restrict__ b, float* __restrict__ out, int cvt)
{
    __shared__ float sm0[8], sm1[8];
    const int row = blockIdx.x, tid = threadIdx.x;
    float4 v = ((const float4*)(x + (long long)row * Dd))[tid];
    float s  = v.x + v.y + v.z + v.w;
    float s2 = v.x * v.x + v.y * v.y + v.z * v.z + v.w * v.w;
    #pragma unroll
    for (int o = 16; o > 0; o >>= 1) {
        s  += __shfl_xor_sync(0xffffffffu, s,  o);
        s2 += __shfl_xor_sync(0xffffffffu, s2, o);
    }
    if ((tid & 31) == 0) { sm0[tid >> 5] = s; sm1[tid >> 5] = s2; }
    __syncthreads();
    if (tid < 32) {
        s  = (tid < 8) ? sm0[tid] : 0.f;
        s2 = (tid < 8) ? sm1[tid] : 0.f;
        #pragma unroll
        for (int o = 4; o > 0; o >>= 1) {
            s  += __shfl_xor_sync(0xffffffffu, s,  o);
            s2 += __shfl_xor_sync(0xffffffffu, s2, o);
        }
        if (tid == 0) { sm0[0] = s; sm1[0] = s2; }
    }
    __syncthreads();
    const float mean = sm0[0] * (1.f / Dd);
    const float var  = sm1[0] * (1.f / Dd) - mean * mean;
    const float rstd = rsqrtf(var + 1e-5f);
    float4 gg = ((const float4*)g)[tid];
    float4 bb = ((const float4*)b)[tid];
    float4 o;
    o.x = (v.x - mean) * rstd * gg.x + bb.x;
    o.y = (v.y - mean) * rstd * gg.y + bb.y;
    o.z = (v.z - mean) * rstd * gg.z + bb.z;
    o.w = (v.w - mean) * rstd * gg.w + bb.w;
    if (cvt) {
        o.x = tf32f(o.x); o.y = tf32f(o.y); o.z = tf32f(o.z); o.w = tf32f(o.w);
    }
    ((float4*)(out + (long long)row * Dd))[tid] = o;
}

// ---------------------------------------------------------------- Softmax (causal row)
__global__ __launch_bounds__(256) void softmax_k(float* __restrict__ attn)
{
    __shared__ float sm[8];
    const int row = blockIdx.x;
    const int q   = row & (Ss - 1);
    float* p = attn + (long long)row * Ss;
    const int tid = threadIdx.x;
    const int k0  = tid * 4;
    float4 v = ((const float4*)p)[tid];

    float m = -1e30f;
    if (k0 + 0 <= q) m = fmaxf(m, v.x);
    if (k0 + 1 <= q) m = fmaxf(m, v.y);
    if (k0 + 2 <= q) m = fmaxf(m, v.z);
    if (k0 + 3 <= q) m = fmaxf(m, v.w);
    #pragma unroll
    for (int o = 16; o > 0; o >>= 1) m = fmaxf(m, __shfl_xor_sync(0xffffffffu, m, o));
    if ((tid & 31) == 0) sm[tid >> 5] = m;
    __syncthreads();
    if (tid < 32) {
        float t = (tid < 8) ? sm[tid] : -1e30f;
        #pragma unroll
        for (int o = 4; o > 0; o >>= 1) t = fmaxf(t, __shfl_xor_sync(0xffffffffu, t, o));
        if (tid == 0) sm[0] = t;
    }
    __syncthreads();
    m = sm[0];
    __syncthreads();

    float4 e;
    e.x = (k0 + 0 <= q) ? __expf(v.x - m) : 0.f;
    e.y = (k0 + 1 <= q) ? __expf(v.y - m) : 0.f;
    e.z = (k0 + 2 <= q) ? __expf(v.z - m) : 0.f;
    e.w = (k0 + 3 <= q) ? __expf(v.w - m) : 0.f;
    float s = e.x + e.y + e.z + e.w;
    #pragma unroll
    for (int o = 16; o > 0; o >>= 1) s += __shfl_xor_sync(0xffffffffu, s, o);
    if ((tid & 31) == 0) sm[tid >> 5] = s;
    __syncthreads();
    if (tid < 32) {
        float t = (tid < 8) ? sm[tid] : 0.f;
        #pragma unroll
        for (int o = 4; o > 0; o >>= 1) t += __shfl_xor_sync(0xffffffffu, t, o);
        if (tid == 0) sm[0] = t;
    }
    __syncthreads();
    const float inv = 1.f / sm[0];
    e.x = tf32f(e.x * inv); e.y = tf32f(e.y * inv);
    e.z = tf32f(e.z * inv); e.w = tf32f(e.w * inv);
    ((float4*)p)[tid] = e;
}

// ---------------------------------------------------------------- Column sums
__global__ __launch_bounds__(256) void colsum_part_k(
    const float* __restrict__ attn, float* __restrict__ part)
{
    const int k  = blockIdx.x * 256 + threadIdx.x;   // 0..1023
    const int b  = blockIdx.y;
    const int rs = blockIdx.z;
    const int RC = Hh * Ss / RSPLIT;                 // 256 rows per split
    const float* base = attn + (long long)b * Hh * Ss * Ss
                             + (long long)rs * RC * Ss + k;
    float s = 0.f;
    #pragma unroll 8
    for (int r = 0; r < RC; r++) s += base[(long long)r * Ss];
    part[(rs * Bb + b) * Ss + k] = s;
}

__global__ __launch_bounds__(256) void colsum_fin_k(
    const float* __restrict__ part, float* __restrict__ amap)
{
    const int i = blockIdx.x * 256 + threadIdx.x;    // 0..2047
    float s = 0.f;
    #pragma unroll
    for (int rs = 0; rs < RSPLIT; rs++) s += part[rs * Bb * Ss + i];
    amap[i] += s;
}

// ---------------------------------------------------------------- misc
__global__ __launch_bounds__(256) void save_ctx_k(
    const float* __restrict__ x, float4* __restrict__ st, int layer)
{
    const int i  = blockIdx.x * 256 + threadIdx.x;   // over BS*D/4
    const int d4 = i & 255;
    const int bs = i >> 8;
    st[((long long)bs * DEPTH + layer) * 256 + d4] = ((const float4*)x)[i];
}

__global__ void zero_k(float* p, int n)
{
    int i = blockIdx.x * 256 + threadIdx.x;
    if (i < n) p[i] = 0.f;
}

// ---------------------------------------------------------------- launcher
extern "C" void kernel_launch(void* const* d_in, const int* in_sizes, int n_in,
                              void* d_out, int out_size)
{
    const float* token = (const float*)d_in[0];
    const float* Wq    = (const float*)d_in[1];
    const float* Wkv   = (const float*)d_in[2];
    const float* Wo    = (const float*)d_in[3];
    const float* b_o   = (const float*)d_in[4];
    const float* g1    = (const float*)d_in[5];
    const float* b1    = (const float*)d_in[6];
    const float* g3    = (const float*)d_in[7];
    const float* b3    = (const float*)d_in[8];
    const float* W1    = (const float*)d_in[9];
    const float* W2    = (const float*)d_in[10];
    const float* gout  = (const float*)d_in[11];
    const float* bout  = (const float*)d_in[12];
    float* out = (float*)d_out;

    float *x, *xn, *qkv, *wqkv, *woc, *w1c, *w2c, *attn, *y, *ff, *red, *part;
    cudaGetSymbolAddress((void**)&x,    g_x);
    cudaGetSymbolAddress((void**)&xn,   g_xn);
    cudaGetSymbolAddress((void**)&qkv,  g_qkv);
    cudaGetSymbolAddress((void**)&wqkv, g_wqkv);
    cudaGetSymbolAddress((void**)&woc,  g_woc);
    cudaGetSymbolAddress((void**)&w1c,  g_w1c);
    cudaGetSymbolAddress((void**)&w2c,  g_w2c);
    cudaGetSymbolAddress((void**)&attn, g_attn);
    cudaGetSymbolAddress((void**)&y,    g_y);
    cudaGetSymbolAddress((void**)&ff,   g_ff);
    cudaGetSymbolAddress((void**)&red,  g_red);
    cudaGetSymbolAddress((void**)&part, g_part);

    // allow 80KB dynamic smem for all GEMM instantiations (idempotent)
    cudaFuncSetAttribute(gemm_tc<0, false, true >, cudaFuncAttributeMaxDynamicSharedMemorySize, GEMM_SMEM);
    cudaFuncSetAttribute(gemm_tc<0, false, false>, cudaFuncAttributeMaxDynamicSharedMemorySize, GEMM_SMEM);
    cudaFuncSetAttribute(gemm_tc<0, true,  false>, cudaFuncAttributeMaxDynamicSharedMemorySize, GEMM_SMEM);
    cudaFuncSetAttribute(gemm_tc<2, false, true >, cudaFuncAttributeMaxDynamicSharedMemorySize, GEMM_SMEM);

    float* out_state = out + (size_t)BS * Dd;
    float* amap      = out_state + (size_t)BS * DEPTH * Dd;

    cudaMemcpyAsync(x, token, sizeof(float) * BS * Dd, cudaMemcpyDeviceToDevice, 0);
    zero_k<<<(BS + 255) / 256, 256>>>(amap, BS);
    pack_w<<<DEPTH * Dd * 3 * Dd / 4 / 256, 256>>>(
        (const float4*)Wq, (const float4*)Wkv, (float4*)wqkv);
    cvt_copy_k<<<DEPTH * Dd * Dd / 4 / 256, 256>>>((const float4*)Wo, (float4*)woc);
    cvt_copy_k<<<DEPTH * Dd * FF / 4 / 256, 256>>>((const float4*)W1, (float4*)w1c);
    cvt_copy_k<<<DEPTH * FF * Dd / 4 / 256, 256>>>((const float4*)W2, (float4*)w2c);

    const float scale = rsqrtf((float)HD);
    const int D3 = 3 * Dd;
    const int NRED = BS * Dd / 4 / 256;

    for (int l = 0; l < DEPTH; l++) {
        // context snapshot
        save_ctx_k<<<BS * Dd / 4 / 256, 256>>>(x, (float4*)out_state, l);
        // LN1 (cvt output: GEMM A operand)
        ln_k<<<BS, 256>>>(x, g1 + l * Dd, b1 + l * Dd, xn, 1);
        // QKV = xn @ [Wq|Wkv]
        gemm_tc<0, false, true><<<dim3(D3 / BN, BS / BM, 1), 128, GEMM_SMEM>>>(
            xn, wqkv + (size_t)l * Dd * D3, qkv,
            Dd, Dd, D3, D3, 0, 0, 0, 0, 0, 0, 1, 1.f, 0);
        // scores = scale * Q @ K^T (causal tile-skip; softmax re-truncates)
        gemm_tc<0, true, false><<<dim3(Ss / BN, Ss / BM, Bb * Hh), 128, GEMM_SMEM>>>(
            qkv, qkv + Dd, attn,
            HD, D3, D3, Ss,
            (long long)Ss * D3, HD,
            (long long)Ss * D3, HD,
            (long long)Hh * Ss * Ss, (long long)Ss * Ss,
            Hh, scale, 1);
        // softmax rows (mask + normalize + cvt)
        softmax_k<<<Bb * Hh * Ss, 256>>>(attn);
        // attention-map column sums
        colsum_part_k<<<dim3(Ss / 256, Bb, RSPLIT), 256>>>(attn, part);
        colsum_fin_k<<<Bb * Ss / 256, 256>>>(part, amap);
        // y = attn @ V (causal K-trim; cvt: feeds Wo GEMM)
        gemm_tc<0, false, true><<<dim3(HD / BN, Ss / BM, Bb * Hh), 128, GEMM_SMEM>>>(
            attn, qkv + 2 * Dd, y,
            Ss, Ss, D3, Dd,
            (long long)Hh * Ss * Ss, (long long)Ss * Ss,
            (long long)Ss * D3, HD,
            (long long)Ss * Dd, HD,
            Hh, 1.f, 2);
        // x += y @ Wo + b_o (split-K=2; partials stay full fp32)
        gemm_tc<0, false, false><<<dim3(Dd / BN, BS / BM, 2), 128, GEMM_SMEM>>>(
            y, woc + (size_t)l * Dd * Dd, red,
            Dd / 2, Dd, Dd, Dd,
            0, Dd / 2, 0, (long long)(Dd / 2) * Dd,
            0, (long long)BS * Dd,
            2, 1.f, 0);
        reduce_add_k<2, true><<<NRED, 256>>>((const float4*)red, (float4*)x, b_o + l * Dd);
        // LN2 (cvt)
        ln_k<<<BS, 256>>>(x, g3 + l * Dd, b3 + l * Dd, xn, 1);
        // ff = gelu(xn @ W1) (cvt: feeds FF2)
        gemm_tc<2, false, true><<<dim3(FF / BN, BS / BM, 1), 128, GEMM_SMEM>>>(
            xn, w1c + (size_t)l * Dd * FF, ff,
            Dd, Dd, FF, FF, 0, 0, 0, 0, 0, 0, 1, 1.f, 0);
        // x += ff @ W2 (split-K=4)
        gemm_tc<0, false, false><<<dim3(Dd / BN, BS / BM, 4), 128, GEMM_SMEM>>>(
            ff, w2c + (size_t)l * FF * Dd, red,
            FF / 4, FF, Dd, Dd,
            0, FF / 4, 0, (long long)(FF / 4) * Dd,
            0, (long long)BS * Dd,
            4, 1.f, 0);
        reduce_add_k<4, false><<<NRED, 256>>>((const float4*)red, (float4*)x, nullptr);
    }
    // final LN -> x_out (exact, no cvt)
    ln_k<<<BS, 256>>>(x, gout, bout, out, 0);
}

// round 7
// speedup vs baseline: 3.3533x; 1.0394x over previous
#include <cuda_runtime.h>
#include <math.h>

// Problem constants
constexpr int Bb    = 2;
constexpr int Ss    = 1024;
constexpr int Dd    = 1024;
constexpr int Hh    = 8;
constexpr int HD    = 128;
constexpr int DEPTH = 8;
constexpr int FF    = 4096;
constexpr int BS    = Bb * Ss;      // 2048
constexpr int RSPLIT = 32;

// Scratch (device globals: allocation-free)
__device__ float g_x  [BS * Dd];
__device__ float g_xn [BS * Dd];
__device__ float g_qkv[(size_t)BS * 3 * Dd];            // q | k | v packed
__device__ float g_wqkvT[(size_t)DEPTH * 3 * Dd * Dd];  // [Wq|Wkv]^T per layer [3D][D], cvt
__device__ float g_woT [(size_t)DEPTH * Dd * Dd];       // Wo^T  [D][D], cvt
__device__ float g_w1T [(size_t)DEPTH * FF * Dd];       // W1^T  [FF][D], cvt
__device__ float g_w2T [(size_t)DEPTH * Dd * FF];       // W2^T  [D][FF], cvt
__device__ float g_attn[(size_t)Bb * Hh * Ss * Ss];     // 64 MB
__device__ float g_y  [BS * Dd];
__device__ float g_ff [(size_t)BS * FF];                // 32 MB
__device__ float g_red[(size_t)4 * BS * Dd];            // split-K partials, 32MB
__device__ float g_part[RSPLIT * Bb * Ss];

// ---------------------------------------------------------------- tf32 helpers
__device__ __forceinline__ unsigned f2tf32(float x) {
    unsigned r;
    asm("cvt.rna.tf32.f32 %0, %1;" : "=r"(r) : "f"(x));
    return r;
}
__device__ __forceinline__ float tf32f(float x) {
    return __uint_as_float(f2tf32(x));
}

__device__ __forceinline__ void mma_tf32(float* c, const unsigned* a, const unsigned* b) {
    asm volatile(
        "mma.sync.aligned.m16n8k8.row.col.f32.tf32.tf32.f32 "
        "{%0,%1,%2,%3}, {%4,%5,%6,%7}, {%8,%9}, {%0,%1,%2,%3};"
        : "+f"(c[0]), "+f"(c[1]), "+f"(c[2]), "+f"(c[3])
        : "r"(a[0]), "r"(a[1]), "r"(a[2]), "r"(a[3]), "r"(b[0]), "r"(b[1]));
}

__device__ __forceinline__ void ldsm4(unsigned& r0, unsigned& r1, unsigned& r2,
                                      unsigned& r3, unsigned addr) {
    asm volatile("ldmatrix.sync.aligned.m8n8.x4.shared.b16 {%0,%1,%2,%3}, [%4];"
                 : "=r"(r0), "=r"(r1), "=r"(r2), "=r"(r3) : "r"(addr));
}

__device__ __forceinline__ void cp_async16(unsigned saddr, const void* gptr) {
    asm volatile("cp.async.cg.shared.global [%0], [%1], 16;"
                 :: "r"(saddr), "l"(gptr));
}
#define CP_COMMIT() asm volatile("cp.async.commit_group;")
#define CP_WAIT2()  asm volatile("cp.async.wait_group 2;")

// ---------------------------------------------------------------- tensor-core GEMM
// C[M,N] = epilogue(alpha * A[M,K] @ B[K,N]);  operands pre-truncated to tf32.
// TRANSB: B stored [N,K] row-major (ldb = K-stride) -> both fragments via ldmatrix
// EPI: 0 = store, 2 = store gelu(acc);  CVT: rna-truncate stored values
// causal: 0 none, 1 = skip tiles above diagonal, 2 = K-trim
#define BM 128
#define BN 128
#define BK 16
#define ALEN 20       // 80B rows: 16B-aligned, conflict-free ldmatrix
#define BLENN 136     // [k][n] row length: t*136+g hits all 32 banks (AV path)
#define BSMAX 2560
#define STAGES 4
constexpr int A_STAGE = BM * ALEN;                       // 2560 floats
constexpr int B_STAGE = BSMAX;                           // 2560 floats
constexpr int GEMM_SMEM = STAGES * (A_STAGE + B_STAGE) * 4;  // 81920 B

template<int EPI, bool TRANSB, bool CVT>
__global__ __launch_bounds__(128, 2) void gemm_tc(
    const float* __restrict__ A, const float* __restrict__ Bg,
    float* __restrict__ C,
    int K, int lda, int ldb, int ldc,
    long long sAo, long long sAi, long long sBo, long long sBi,
    long long sCo, long long sCi, int zdiv,
    float alpha, int causal)
{
    const int bm = blockIdx.y * BM;
    const int bn = blockIdx.x * BN;
    if (causal == 1 && bn >= bm + BM) return;
    const int Keff = (causal == 2) ? min(K, bm + BM) : K;

    const int z  = blockIdx.z;
    const int zo = z / zdiv;
    const int zi = z - zo * zdiv;
    A  += zo * sAo + zi * sAi;
    Bg += zo * sBo + zi * sBi;
    C  += zo * sCo + zi * sCi;

    extern __shared__ float smem[];
    float* AsBase = smem;                        // [STAGES][A_STAGE]  [m][k]
    float* BsBase = smem + STAGES * A_STAGE;     // [STAGES][B_STAGE]  trans:[n][k] else [k][n]

    const int tid  = threadIdx.x;
    const int lane = tid & 31;
    const int warp = tid >> 5;              // 0..3
    const int wm   = (warp & 1) * 64;       // warp tile 64(M) x 64(N)
    const int wn   = (warp >> 1) * 64;
    const int g    = lane >> 2;             // 0..7
    const int t    = lane & 3;              // 0..3

    // ldmatrix per-lane offsets
    const int lp = lane >> 3;
    const int lr = lane & 7;
    const int aRowOff = (lp & 1) * 8 + lr;
    const int aColOff = (lp >> 1) * 4;
    const int bRowOff = (lp >> 1) * 8 + lr;   // [n][k] b-frag ldsm (trans)
    const int bColOff = (lp & 1) * 4;
    const unsigned asb = (unsigned)__cvta_generic_to_shared(AsBase);
    const unsigned bsb = (unsigned)__cvta_generic_to_shared(BsBase);

    float acc[4][8][4];
    #pragma unroll
    for (int i = 0; i < 4; i++)
        #pragma unroll
        for (int j = 0; j < 8; j++)
            #pragma unroll
            for (int r = 0; r < 4; r++) acc[i][j][r] = 0.f;

    // global->smem cp.async mappings (128 threads, 16B each)
    const int arow = tid >> 2;              // 0..31 (+32h)
    const int ac4  = (tid & 3) * 4;         // k offset
    const int bkr  = tid >> 5;              // 0..3 (+4h)  (non-trans)
    const int bnc  = (tid & 31) * 4;        // n offset    (non-trans)

    auto issueStage = [&](int s, int k0) {
        const unsigned aB = asb + (unsigned)(s * A_STAGE * 4);
        #pragma unroll
        for (int h = 0; h < 4; h++)
            cp_async16(aB + (unsigned)(((arow + 32 * h) * ALEN + ac4) * 4),
                       &A[(long long)(bm + arow + 32 * h) * lda + k0 + ac4]);
        const unsigned bB = bsb + (unsigned)(s * B_STAGE * 4);
        if (!TRANSB) {
            #pragma unroll
            for (int h = 0; h < 4; h++)
                cp_async16(bB + (unsigned)(((bkr + 4 * h) * BLENN + bnc) * 4),
                           &Bg[(long long)(k0 + bkr + 4 * h) * ldb + bn + bnc]);
        } else {
            #pragma unroll
            for (int h = 0; h < 4; h++)
                cp_async16(bB + (unsigned)(((arow + 32 * h) * ALEN + ac4) * 4),
                           &Bg[(long long)(bn + arow + 32 * h) * ldb + k0 + ac4]);
        }
    };

    auto compute = [&](int p) {
        const float* Bsp = BsBase + p * B_STAGE;
        const unsigned abase = asb + (unsigned)(p * A_STAGE * 4)
                             + (unsigned)(((wm + aRowOff) * ALEN + aColOff) * 4);
        const unsigned bbase = bsb + (unsigned)(p * B_STAGE * 4)
                             + (unsigned)(((wn + bRowOff) * ALEN + bColOff) * 4);
        #pragma unroll
        for (int ks = 0; ks < 2; ks++) {
            const int kk = ks * 8;
            unsigned af[4][4], bf[8][2];
            #pragma unroll
            for (int i = 0; i < 4; i++)
                ldsm4(af[i][0], af[i][1], af[i][2], af[i][3],
                      abase + (unsigned)((i * 16 * ALEN + kk) * 4));
            if (TRANSB) {
                #pragma unroll
                for (int jp = 0; jp < 4; jp++)
                    ldsm4(bf[2 * jp][0], bf[2 * jp][1], bf[2 * jp + 1][0], bf[2 * jp + 1][1],
                          bbase + (unsigned)((jp * 16 * ALEN + kk) * 4));
            } else {
                #pragma unroll
                for (int j = 0; j < 8; j++) {
                    int c0 = wn + j * 8 + g;
                    bf[j][0] = __float_as_uint(Bsp[(kk + t    ) * BLENN + c0]);
                    bf[j][1] = __float_as_uint(Bsp[(kk + t + 4) * BLENN + c0]);
                }
            }
            #pragma unroll
            for (int i = 0; i < 4; i++)
                #pragma unroll
                for (int j = 0; j < 8; j++)
                    mma_tf32(acc[i][j], af[i], bf[j]);
        }
    };

    const int nk = Keff / BK;
    #pragma unroll
    for (int s = 0; s < STAGES - 1; s++) {
        issueStage(s, s * BK);
        CP_COMMIT();
    }
    for (int kt = 0; kt < nk; kt++) {
        CP_WAIT2();
        __syncthreads();
        compute(kt % STAGES);
        if (kt + STAGES - 1 < nk)
            issueStage((kt + STAGES - 1) % STAGES, (kt + STAGES - 1) * BK);
        CP_COMMIT();
    }

    // Epilogue
    #pragma unroll
    for (int i = 0; i < 4; i++) {
        #pragma unroll
        for (int j = 0; j < 8; j++) {
            const long long row = bm + wm + i * 16 + g;
            const int       col = bn + wn + j * 8 + 2 * t;
            float2 v0 = make_float2(acc[i][j][0] * alpha, acc[i][j][1] * alpha);
            float2 v1 = make_float2(acc[i][j][2] * alpha, acc[i][j][3] * alpha);
            float* cp0 = &C[row * (long long)ldc + col];
            float* cp1 = &C[(row + 8) * (long long)ldc + col];
            if (EPI == 2) {
                const float c = 0.70710678118654752f;
                v0.x = 0.5f * v0.x * erfcf(-v0.x * c);
                v0.y = 0.5f * v0.y * erfcf(-v0.y * c);
                v1.x = 0.5f * v1.x * erfcf(-v1.x * c);
                v1.y = 0.5f * v1.y * erfcf(-v1.y * c);
            }
            if (CVT) {
                v0.x = tf32f(v0.x); v0.y = tf32f(v0.y);
                v1.x = tf32f(v1.x); v1.y = tf32f(v1.y);
            }
            *(float2*)cp0 = v0;
            *(float2*)cp1 = v1;
        }
    }
}

// ---------------------------------------------------------------- split-K reduce (+optional snapshot of new x)
template<int P, bool BIAS, bool SNAP>
__global__ __launch_bounds__(256) void reduce_add_k(
    const float4* __restrict__ part, float4* __restrict__ x,
    const float* __restrict__ bias, float4* __restrict__ st, int layer)
{
    const int i = blockIdx.x * 256 + threadIdx.x;    // over BS*Dd/4
    constexpr int N4 = BS * Dd / 4;
    float4 s = part[i];
    #pragma unroll
    for (int p = 1; p < P; p++) {
        float4 v = part[(size_t)p * N4 + i];
        s.x += v.x; s.y += v.y; s.z += v.z; s.w += v.w;
    }
    if (BIAS) {
        float4 bb = ((const float4*)bias)[i & (Dd / 4 - 1)];
        s.x += bb.x; s.y += bb.y; s.z += bb.z; s.w += bb.w;
    }
    float4 o = x[i];
    o.x += s.x; o.y += s.y; o.z += s.z; o.w += s.w;
    x[i] = o;
    if (SNAP)
        st[((long long)(i >> 8) * DEPTH + layer) * 256 + (i & 255)] = o;
}

// ---------------------------------------------------------------- transpose+cvt: dst[c][r] = tf32(src[r][c])
__global__ __launch_bounds__(256) void transpose_cvt_k(
    const float* __restrict__ src, float* __restrict__ dst,
    int R, int C, long long sSrc, long long sDst)
{
    __shared__ float tile[32][33];
    src += blockIdx.z * sSrc;
    dst += blockIdx.z * sDst;
    const int c0 = blockIdx.x * 32, r0 = blockIdx.y * 32;
    const int tx = threadIdx.x & 31, ty = threadIdx.x >> 5;   // ty 0..7
    #pragma unroll
    for (int dy = 0; dy < 32; dy += 8)
        tile[ty + dy][tx] = src[(long long)(r0 + ty + dy) * C + c0 + tx];
    __syncthreads();
    #pragma unroll
    for (int dy = 0; dy < 32; dy += 8)
        dst[(long long)(c0 + ty + dy) * R + r0 + tx] = tf32f(tile[tx][ty + dy]);
}

// ---------------------------------------------------------------- LayerNorm
__global__ __launch_bounds__(256) void ln_k(
    const float* __restrict__ x, const float* __restrict__ g,
    const float* __restrict__ b, float* __restrict__ out, int cvt)
{
    __shared__ float sm0[8], sm1[8];
    const int row = blockIdx.x, tid = threadIdx.x;
    float4 v = ((const float4*)(x + (long long)row * Dd))[tid];
    float s  = v.x + v.y + v.z + v.w;
    float s2 = v.x * v.x + v.y * v.y + v.z * v.z + v.w * v.w;
    #pragma unroll
    for (int o = 16; o > 0; o >>= 1) {
        s  += __shfl_xor_sync(0xffffffffu, s,  o);
        s2 += __shfl_xor_sync(0xffffffffu, s2, o);
    }
    if ((tid & 31) == 0) { sm0[tid >> 5] = s; sm1[tid >> 5] = s2; }
    __syncthreads();
    if (tid < 32) {
        s  = (tid < 8) ? sm0[tid] : 0.f;
        s2 = (tid < 8) ? sm1[tid] : 0.f;
        #pragma unroll
        for (int o = 4; o > 0; o >>= 1) {
            s  += __shfl_xor_sync(0xffffffffu, s,  o);
            s2 += __shfl_xor_sync(0xffffffffu, s2, o);
        }
        if (tid == 0) { sm0[0] = s; sm1[0] = s2; }
    }
    __syncthreads();
    const float mean = sm0[0] * (1.f / Dd);
    const float var  = sm1[0] * (1.f / Dd) - mean * mean;
    const float rstd = rsqrtf(var + 1e-5f);
    float4 gg = ((const float4*)g)[tid];
    float4 bb = ((const float4*)b)[tid];
    float4 o;
    o.x = (v.x - mean) * rstd * gg.x + bb.x;
    o.y = (v.y - mean) * rstd * gg.y + bb.y;
    o.z = (v.z - mean) * rstd * gg.z + bb.z;
    o.w = (v.w - mean) * rstd * gg.w + bb.w;
    if (cvt) {
        o.x = tf32f(o.x); o.y = tf32f(o.y); o.z = tf32f(o.z); o.w = tf32f(o.w);
    }
    ((float4*)(out + (long long)row * Dd))[tid] = o;
}

// ---------------------------------------------------------------- Softmax (causal row)
__global__ __launch_bounds__(256) void softmax_k(float* __restrict__ attn)
{
    __shared__ float sm[8];
    const int row = blockIdx.x;
    const int q   = row & (Ss - 1);
    float* p = attn + (long long)row * Ss;
    const int tid = threadIdx.x;
    const int k0  = tid * 4;
    float4 v = ((const float4*)p)[tid];

    float m = -1e30f;
    if (k0 + 0 <= q) m = fmaxf(m, v.x);
    if (k0 + 1 <= q) m = fmaxf(m, v.y);
    if (k0 + 2 <= q) m = fmaxf(m, v.z);
    if (k0 + 3 <= q) m = fmaxf(m, v.w);
    #pragma unroll
    for (int o = 16; o > 0; o >>= 1) m = fmaxf(m, __shfl_xor_sync(0xffffffffu, m, o));
    if ((tid & 31) == 0) sm[tid >> 5] = m;
    __syncthreads();
    if (tid < 32) {
        float t = (tid < 8) ? sm[tid] : -1e30f;
        #pragma unroll
        for (int o = 4; o > 0; o >>= 1) t = fmaxf(t, __shfl_xor_sync(0xffffffffu, t, o));
        if (tid == 0) sm[0] = t;
    }
    __syncthreads();
    m = sm[0];
    __syncthreads();

    float4 e;
    e.x = (k0 + 0 <= q) ? __expf(v.x - m) : 0.f;
    e.y = (k0 + 1 <= q) ? __expf(v.y - m) : 0.f;
    e.z = (k0 + 2 <= q) ? __expf(v.z - m) : 0.f;
    e.w = (k0 + 3 <= q) ? __expf(v.w - m) : 0.f;
    float s = e.x + e.y + e.z + e.w;
    #pragma unroll
    for (int o = 16; o > 0; o >>= 1) s += __shfl_xor_sync(0xffffffffu, s, o);
    if ((tid & 31) == 0) sm[tid >> 5] = s;
    __syncthreads();
    if (tid < 32) {
        float t = (tid < 8) ? sm[tid] : 0.f;
        #pragma unroll
        for (int o = 4; o > 0; o >>= 1) t += __shfl_xor_sync(0xffffffffu, t, o);
        if (tid == 0) sm[0] = t;
    }
    __syncthreads();
    const float inv = 1.f / sm[0];
    e.x = tf32f(e.x * inv); e.y = tf32f(e.y * inv);
    e.z = tf32f(e.z * inv); e.w = tf32f(e.w * inv);
    ((float4*)p)[tid] = e;
}

// ---------------------------------------------------------------- Column sums
__global__ __launch_bounds__(256) void colsum_part_k(
    const float* __restrict__ attn, float* __restrict__ part)
{
    const int k  = blockIdx.x * 256 + threadIdx.x;   // 0..1023
    const int b  = blockIdx.y;
    const int rs = blockIdx.z;
    const int RC = Hh * Ss / RSPLIT;                 // 256 rows per split
    const float* base = attn + (long long)b * Hh * Ss * Ss
                             + (long long)rs * RC * Ss + k;
    float s = 0.f;
    #pragma unroll 8
    for (int r = 0; r < RC; r++) s += base[(long long)r * Ss];
    part[(rs * Bb + b) * Ss + k] = s;
}

__global__ __launch_bounds__(256) void colsum_fin_k(
    const float* __restrict__ part, float* __restrict__ amap)
{
    const int i = blockIdx.x * 256 + threadIdx.x;    // 0..2047
    float s = 0.f;
    #pragma unroll
    for (int rs = 0; rs < RSPLIT; rs++) s += part[rs * Bb * Ss + i];
    amap[i] += s;
}

// ---------------------------------------------------------------- misc
__global__ __launch_bounds__(256) void init_x_snap_k(
    const float4* __restrict__ token, float4* __restrict__ x,
    float4* __restrict__ st)
{
    const int i = blockIdx.x * 256 + threadIdx.x;    // over BS*Dd/4
    float4 v = token[i];
    x[i] = v;
    st[((long long)(i >> 8) * DEPTH + 0) * 256 + (i & 255)] = v;
}

__global__ void zero_k(float* p, int n)
{
    int i = blockIdx.x * 256 + threadIdx.x;
    if (i < n) p[i] = 0.f;
}

// ---------------------------------------------------------------- launcher
extern "C" void kernel_launch(void* const* d_in, const int* in_sizes, int n_in,
                              void* d_out, int out_size)
{
    const float* token = (const float*)d_in[0];
    const float* Wq    = (const float*)d_in[1];
    const float* Wkv   = (const float*)d_in[2];
    const float* Wo    = (const float*)d_in[3];
    const float* b_o   = (const float*)d_in[4];
    const float* g1    = (const float*)d_in[5];
    const float* b1    = (const float*)d_in[6];
    const float* g3    = (const float*)d_in[7];
    const float* b3    = (const float*)d_in[8];
    const float* W1    = (const float*)d_in[9];
    const float* W2    = (const float*)d_in[10];
    const float* gout  = (const float*)d_in[11];
    const float* bout  = (const float*)d_in[12];
    float* out = (float*)d_out;

    float *x, *xn, *qkv, *wqkvT, *woT, *w1T, *w2T, *attn, *y, *ff, *red, *part;
    cudaGetSymbolAddress((void**)&x,     g_x);
    cudaGetSymbolAddress((void**)&xn,    g_xn);
    cudaGetSymbolAddress((void**)&qkv,   g_qkv);
    cudaGetSymbolAddress((void**)&wqkvT, g_wqkvT);
    cudaGetSymbolAddress((void**)&woT,   g_woT);
    cudaGetSymbolAddress((void**)&w1T,   g_w1T);
    cudaGetSymbolAddress((void**)&w2T,   g_w2T);
    cudaGetSymbolAddress((void**)&attn,  g_attn);
    cudaGetSymbolAddress((void**)&y,     g_y);
    cudaGetSymbolAddress((void**)&ff,    g_ff);
    cudaGetSymbolAddress((void**)&red,   g_red);
    cudaGetSymbolAddress((void**)&part,  g_part);

    cudaFuncSetAttribute(gemm_tc<0, true,  true >, cudaFuncAttributeMaxDynamicSharedMemorySize, GEMM_SMEM);
    cudaFuncSetAttribute(gemm_tc<0, true,  false>, cudaFuncAttributeMaxDynamicSharedMemorySize, GEMM_SMEM);
    cudaFuncSetAttribute(gemm_tc<0, false, true >, cudaFuncAttributeMaxDynamicSharedMemorySize, GEMM_SMEM);
    cudaFuncSetAttribute(gemm_tc<2, true,  true >, cudaFuncAttributeMaxDynamicSharedMemorySize, GEMM_SMEM);

    float* out_state = out + (size_t)BS * Dd;
    float* amap      = out_state + (size_t)BS * DEPTH * Dd;

    init_x_snap_k<<<BS * Dd / 4 / 256, 256>>>((const float4*)token, (float4*)x,
                                              (float4*)out_state);
    zero_k<<<(BS + 255) / 256, 256>>>(amap, BS);

    // weight transpose+cvt: dst layouts are [N][K]
    const int D3 = 3 * Dd;
    transpose_cvt_k<<<dim3(Dd / 32, Dd / 32, DEPTH), 256>>>(
        Wq, wqkvT, Dd, Dd, (long long)Dd * Dd, (long long)D3 * Dd);
    transpose_cvt_k<<<dim3(2 * Dd / 32, Dd / 32, DEPTH), 256>>>(
        Wkv, wqkvT + (size_t)Dd * Dd, Dd, 2 * Dd,
        (long long)Dd * 2 * Dd, (long long)D3 * Dd);
    transpose_cvt_k<<<dim3(Dd / 32, Dd / 32, DEPTH), 256>>>(
        Wo, woT, Dd, Dd, (long long)Dd * Dd, (long long)Dd * Dd);
    transpose_cvt_k<<<dim3(FF / 32, Dd / 32, DEPTH), 256>>>(
        W1, w1T, Dd, FF, (long long)Dd * FF, (long long)Dd * FF);
    transpose_cvt_k<<<dim3(Dd / 32, FF / 32, DEPTH), 256>>>(
        W2, w2T, FF, Dd, (long long)FF * Dd, (long long)FF * Dd);

    const float scale = rsqrtf((float)HD);
    const int NRED = BS * Dd / 4 / 256;

    for (int l = 0; l < DEPTH; l++) {
        // LN1 (cvt output: GEMM A operand)
        ln_k<<<BS, 256>>>(x, g1 + l * Dd, b1 + l * Dd, xn, 1);
        // QKV = xn @ [Wq|Wkv]  (B = wqkvT [3D][D], TRANSB)
        gemm_tc<0, true, true><<<dim3(D3 / BN, BS / BM, 1), 128, GEMM_SMEM>>>(
            xn, wqkvT + (size_t)l * D3 * Dd, qkv,
            Dd, Dd, Dd, D3, 0, 0, 0, 0, 0, 0, 1, 1.f, 0);
        // scores = scale * Q @ K^T (causal tile-skip)
        gemm_tc<0, true, false><<<dim3(Ss / BN, Ss / BM, Bb * Hh), 128, GEMM_SMEM>>>(
            qkv, qkv + Dd, attn,
            HD, D3, D3, Ss,
            (long long)Ss * D3, HD,
            (long long)Ss * D3, HD,
            (long long)Hh * Ss * Ss, (long long)Ss * Ss,
            Hh, scale, 1);
        // softmax rows (mask + normalize + cvt)
        softmax_k<<<Bb * Hh * Ss, 256>>>(attn);
        // attention-map column sums
        colsum_part_k<<<dim3(Ss / 256, Bb, RSPLIT), 256>>>(attn, part);
        colsum_fin_k<<<Bb * Ss / 256, 256>>>(part, amap);
        // y = attn @ V (non-trans; causal K-trim; cvt)
        gemm_tc<0, false, true><<<dim3(HD / BN, Ss / BM, Bb * Hh), 128, GEMM_SMEM>>>(
            attn, qkv + 2 * Dd, y,
            Ss, Ss, D3, Dd,
            (long long)Hh * Ss * Ss, (long long)Ss * Ss,
            (long long)Ss * D3, HD,
            (long long)Ss * Dd, HD,
            Hh, 1.f, 2);
        // x += y @ Wo + b_o  (B = woT [D][D] TRANSB; split-K=2)
        gemm_tc<0, true, false><<<dim3(Dd / BN, BS / BM, 2), 128, GEMM_SMEM>>>(
            y, woT + (size_t)l * Dd * Dd, red,
            Dd / 2, Dd, Dd, Dd,
            0, Dd / 2, 0, Dd / 2,
            0, (long long)BS * Dd,
            2, 1.f, 0);
        reduce_add_k<2, true, false><<<NRED, 256>>>(
            (const float4*)red, (float4*)x, b_o + l * Dd, nullptr, 0);
        // LN2 (cvt)
        ln_k<<<BS, 256>>>(x, g3 + l * Dd, b3 + l * Dd, xn, 1);
        // ff = gelu(xn @ W1)  (B = w1T [FF][D] TRANSB)
        gemm_tc<2, true, true><<<dim3(FF / BN, BS / BM, 1), 128, GEMM_SMEM>>>(
            xn, w1T + (size_t)l * FF * Dd, ff,
            Dd, Dd, Dd, FF, 0, 0, 0, 0, 0, 0, 1, 1.f, 0);
        // x += ff @ W2  (B = w2T [D][FF] TRANSB; split-K=4)
        gemm_tc<0, true, false><<<dim3(Dd / BN, BS / BM, 4), 128, GEMM_SMEM>>>(
            ff, w2T + (size_t)l * Dd * FF, red,
            FF / 4, FF, FF, Dd,
            0, FF / 4, 0, FF / 4,
            0, (long long)BS * Dd,
            4, 1.f, 0);
        if (l < DEPTH - 1)
            reduce_add_k<4, false, true><<<NRED, 256>>>(
                (const float4*)red, (float4*)x, nullptr, (float4*)out_state, l + 1);
        else
            reduce_add_k<4, false, false><<<NRED, 256>>>(
                (const float4*)red, (float4*)x, nullptr, nullptr, 0);
    }
    // final LN -> x_out (exact, no cvt)
    ln_k<<<BS, 256>>>(x, gout, bout, out, 0);
}

// round 9
// speedup vs baseline: 4.5323x; 1.3516x over previous
#include <cuda_runtime.h>
#include <cuda_fp16.h>
#include <math.h>
#include <stdint.h>

// Problem constants
constexpr int Bb    = 2;
constexpr int Ss    = 1024;
constexpr int Dd    = 1024;
constexpr int Hh    = 8;
constexpr int HD    = 128;
constexpr int DEPTH = 8;
constexpr int FF    = 4096;
constexpr int BS    = Bb * Ss;      // 2048
constexpr int RSPLIT = 32;

// Scratch (device globals: allocation-free)
__device__ float  g_x  [BS * Dd];
__device__ __half g_xn [BS * Dd];
__device__ __half g_qkv[(size_t)BS * 3 * Dd];            // q | k | v packed (half)
__device__ __half g_wqkvT[(size_t)DEPTH * 3 * Dd * Dd];  // [Wq|Wkv]^T [3D][D] half
__device__ __half g_woT [(size_t)DEPTH * Dd * Dd];       // Wo^T  [D][D] half
__device__ __half g_w1T [(size_t)DEPTH * FF * Dd];       // W1^T  [FF][D] half
__device__ __half g_w2T [(size_t)DEPTH * Dd * FF];       // W2^T  [D][FF] half
__device__ __half g_attn[(size_t)Bb * Hh * Ss * Ss];     // 32 MB
__device__ __half g_y  [BS * Dd];
__device__ __half g_ff [(size_t)BS * FF];
__device__ float  g_red[(size_t)4 * BS * Dd];            // split-K partials (fp32)
__device__ float  g_part[RSPLIT * Bb * Ss];

// ---------------------------------------------------------------- mma / ldmatrix
__device__ __forceinline__ void mma_f16(float* c, const unsigned* a, const unsigned* b) {
    asm volatile(
        "mma.sync.aligned.m16n8k16.row.col.f32.f16.f16.f32 "
        "{%0,%1,%2,%3}, {%4,%5,%6,%7}, {%8,%9}, {%0,%1,%2,%3};"
        : "+f"(c[0]), "+f"(c[1]), "+f"(c[2]), "+f"(c[3])
        : "r"(a[0]), "r"(a[1]), "r"(a[2]), "r"(a[3]), "r"(b[0]), "r"(b[1]));
}
__device__ __forceinline__ void ldsm4(unsigned& r0, unsigned& r1, unsigned& r2,
                                      unsigned& r3, unsigned addr) {
    asm volatile("ldmatrix.sync.aligned.m8n8.x4.shared.b16 {%0,%1,%2,%3}, [%4];"
                 : "=r"(r0), "=r"(r1), "=r"(r2), "=r"(r3) : "r"(addr));
}
__device__ __forceinline__ void ldsm4t(unsigned& r0, unsigned& r1, unsigned& r2,
                                       unsigned& r3, unsigned addr) {
    asm volatile("ldmatrix.sync.aligned.m8n8.x4.trans.shared.b16 {%0,%1,%2,%3}, [%4];"
                 : "=r"(r0), "=r"(r1), "=r"(r2), "=r"(r3) : "r"(addr));
}
__device__ __forceinline__ void cp_async16(unsigned saddr, const void* gptr) {
    asm volatile("cp.async.cg.shared.global [%0], [%1], 16;"
                 :: "r"(saddr), "l"(gptr));
}
#define CP_COMMIT() asm volatile("cp.async.commit_group;")
#define CP_WAIT2()  asm volatile("cp.async.wait_group 2;")

// ---------------------------------------------------------------- fp16 tensor-core GEMM
// C[M,N] = epi(alpha * A[M,K] @ B), A half [M][K].
// TRANSB: B half [N][K] (ldb = K-stride). else B half [K][N] (AV path).
// EPI: 0 = store, 2 = gelu.  OUTHALF: store half2, else fp32 (split-K partials).
// causal: 0 none, 1 = skip tiles above diagonal, 2 = K-trim.
#define BM 128
#define BN 128
#define BKH 32          // halves per k-tile
#define AL 40           // A / B(trans) row length in halves: 80B rows, conflict-free ldsm
#define BLN 136         // B(non-trans) [k][n] row length in halves: 272B rows
#define STAGES 4
constexpr int AH_ST = BM * AL;                 // 5120 halves
constexpr int BH_ST = 5120;                    // max(128*40, 32*136)
constexpr int GEMM_SMEM = STAGES * (AH_ST + BH_ST) * 2;   // 81920 B

template<int EPI, bool TRANSB, bool OUTHALF>
__global__ __launch_bounds__(128, 2) void gemm_h(
    const __half* __restrict__ A, const __half* __restrict__ Bg,
    void* __restrict__ Cv,
    int K, int lda, int ldb, int ldc,
    long long sAo, long long sAi, long long sBo, long long sBi,
    long long sCo, long long sCi, int zdiv,
    float alpha, int causal)
{
    const int bm = blockIdx.y * BM;
    const int bn = blockIdx.x * BN;
    if (causal == 1 && bn >= bm + BM) return;
    const int Keff = (causal == 2) ? min(K, bm + BM) : K;

    const int z  = blockIdx.z;
    const int zo = z / zdiv;
    const int zi = z - zo * zdiv;
    A  += zo * sAo + zi * sAi;
    Bg += zo * sBo + zi * sBi;
    const long long coff = zo * sCo + zi * sCi;
    __half* Ch = (__half*)Cv + coff;
    float*  Cf = (float*)Cv + coff;

    extern __shared__ __align__(16) char smem_raw[];
    const unsigned asb = (unsigned)__cvta_generic_to_shared(smem_raw);
    const unsigned bsb = asb + (unsigned)(STAGES * AH_ST * 2);

    const int tid  = threadIdx.x;
    const int lane = tid & 31;
    const int warp = tid >> 5;
    const int wm   = (warp & 1) * 64;       // warp tile 64(M) x 64(N)
    const int wn   = (warp >> 1) * 64;
    const int g    = lane >> 2;
    const int t    = lane & 3;

    const int lp = lane >> 3;
    const int lr = lane & 7;
    const int aRowOff  = (lp & 1) * 8 + lr;     // A frag (and rows of trans-B via bRowOff)
    const int aColOff  = (lp >> 1) * 8;         // halves
    const int bRowOff  = (lp >> 1) * 8 + lr;    // trans-B frag (n rows)
    const int bColOff  = (lp & 1) * 8;
    const int ntRowOff = (lp & 1) * 8 + lr;     // non-trans B (k rows)
    const int ntColOff = (lp >> 1) * 8;

    float acc[4][8][4];
    #pragma unroll
    for (int i = 0; i < 4; i++)
        #pragma unroll
        for (int j = 0; j < 8; j++)
            #pragma unroll
            for (int r = 0; r < 4; r++) acc[i][j][r] = 0.f;

    auto issue = [&](int s, int k0) {
        const unsigned aB = asb + (unsigned)(s * AH_ST * 2);
        #pragma unroll
        for (int h = 0; h < 4; h++) {
            int row = (tid >> 2) + 32 * h;
            cp_async16(aB + (unsigned)((row * AL + (tid & 3) * 8) * 2),
                       &A[(long long)(bm + row) * lda + k0 + (tid & 3) * 8]);
        }
        const unsigned bB = bsb + (unsigned)(s * BH_ST * 2);
        if (TRANSB) {
            #pragma unroll
            for (int h = 0; h < 4; h++) {
                int row = (tid >> 2) + 32 * h;
                cp_async16(bB + (unsigned)((row * AL + (tid & 3) * 8) * 2),
                           &Bg[(long long)(bn + row) * ldb + k0 + (tid & 3) * 8]);
            }
        } else {
            #pragma unroll
            for (int h = 0; h < 4; h++) {
                int idx = h * 128 + tid;       // 512 chunks of 16B
                int kr  = idx >> 4;            // 0..31
                int ch  = idx & 15;            // 16 chunks per row
                cp_async16(bB + (unsigned)((kr * BLN + ch * 8) * 2),
                           &Bg[(long long)(k0 + kr) * ldb + bn + ch * 8]);
            }
        }
    };

    auto compute = [&](int p) {
        const unsigned abase = asb + (unsigned)(p * AH_ST * 2)
                             + (unsigned)(((wm + aRowOff) * AL + aColOff) * 2);
        unsigned bbase;
        if (TRANSB)
            bbase = bsb + (unsigned)(p * BH_ST * 2)
                  + (unsigned)(((wn + bRowOff) * AL + bColOff) * 2);
        else
            bbase = bsb + (unsigned)(p * BH_ST * 2)
                  + (unsigned)((ntRowOff * BLN + wn + ntColOff) * 2);
        #pragma unroll
        for (int ks = 0; ks < 2; ks++) {
            const int kk = ks * 16;
            unsigned af[4][4], bf[8][2];
            #pragma unroll
            for (int i = 0; i < 4; i++)
                ldsm4(af[i][0], af[i][1], af[i][2], af[i][3],
                      abase + (unsigned)((i * 16 * AL + kk) * 2));
            if (TRANSB) {
                #pragma unroll
                for (int jp = 0; jp < 4; jp++) {
                    unsigned r0, r1, r2, r3;
                    ldsm4(r0, r1, r2, r3, bbase + (unsigned)((jp * 16 * AL + kk) * 2));
                    bf[2 * jp][0] = r0; bf[2 * jp][1] = r1;
                    bf[2 * jp + 1][0] = r2; bf[2 * jp + 1][1] = r3;
                }
            } else {
                #pragma unroll
                for (int jp = 0; jp < 4; jp++) {
                    unsigned r0, r1, r2, r3;
                    ldsm4t(r0, r1, r2, r3,
                           bbase + (unsigned)((kk * BLN + jp * 16) * 2));
                    bf[2 * jp][0] = r0; bf[2 * jp][1] = r1;
                    bf[2 * jp + 1][0] = r2; bf[2 * jp + 1][1] = r3;
                }
            }
            #pragma unroll
            for (int i = 0; i < 4; i++)
                #pragma unroll
                for (int j = 0; j < 8; j++)
                    mma_f16(acc[i][j], af[i], bf[j]);
        }
    };

    const int nk = Keff / BKH;
    #pragma unroll
    for (int s = 0; s < STAGES - 1; s++) {
        if (s < nk) issue(s, s * BKH);
        CP_COMMIT();
    }
    for (int kt = 0; kt < nk; kt++) {
        CP_WAIT2();
        __syncthreads();
        compute(kt % STAGES);
        if (kt + STAGES - 1 < nk)
            issue((kt + STAGES - 1) % STAGES, (kt + STAGES - 1) * BKH);
        CP_COMMIT();
    }

    // Epilogue
    #pragma unroll
    for (int i = 0; i < 4; i++) {
        #pragma unroll
        for (int j = 0; j < 8; j++) {
            const long long row = bm + wm + i * 16 + g;
            const int       col = bn + wn + j * 8 + 2 * t;
            float2 v0 = make_float2(acc[i][j][0] * alpha, acc[i][j][1] * alpha);
            float2 v1 = make_float2(acc[i][j][2] * alpha, acc[i][j][3] * alpha);
            if (EPI == 2) {
                const float c = 0.70710678118654752f;
                v0.x = 0.5f * v0.x * erfcf(-v0.x * c);
                v0.y = 0.5f * v0.y * erfcf(-v0.y * c);
                v1.x = 0.5f * v1.x * erfcf(-v1.x * c);
                v1.y = 0.5f * v1.y * erfcf(-v1.y * c);
            }
            if (OUTHALF) {
                *(__half2*)&Ch[row * (long long)ldc + col]       = __floats2half2_rn(v0.x, v0.y);
                *(__half2*)&Ch[(row + 8) * (long long)ldc + col] = __floats2half2_rn(v1.x, v1.y);
            } else {
                *(float2*)&Cf[row * (long long)ldc + col]       = v0;
                *(float2*)&Cf[(row + 8) * (long long)ldc + col] = v1;
            }
        }
    }
}

// ---------------------------------------------------------------- split-K reduce (+optional snapshot)
template<int P, bool BIAS, bool SNAP>
__global__ __launch_bounds__(256) void reduce_add_k(
    const float4* __restrict__ part, float4* __restrict__ x,
    const float* __restrict__ bias, float4* __restrict__ st, int layer)
{
    const int i = blockIdx.x * 256 + threadIdx.x;
    constexpr int N4 = BS * Dd / 4;
    float4 s = part[i];
    #pragma unroll
    for (int p = 1; p < P; p++) {
        float4 v = part[(size_t)p * N4 + i];
        s.x += v.x; s.y += v.y; s.z += v.z; s.w += v.w;
    }
    if (BIAS) {
        float4 bb = ((const float4*)bias)[i & (Dd / 4 - 1)];
        s.x += bb.x; s.y += bb.y; s.z += bb.z; s.w += bb.w;
    }
    float4 o = x[i];
    o.x += s.x; o.y += s.y; o.z += s.z; o.w += s.w;
    x[i] = o;
    if (SNAP)
        st[((long long)(i >> 8) * DEPTH + layer) * 256 + (i & 255)] = o;
}

// ---------------------------------------------------------------- transpose + cvt to half
__global__ __launch_bounds__(256) void transpose_cvt_k(
    const float* __restrict__ src, __half* __restrict__ dst,
    int R, int C, long long sSrc, long long sDst)
{
    __shared__ float tile[32][33];
    src += blockIdx.z * sSrc;
    dst += blockIdx.z * sDst;
    const int c0 = blockIdx.x * 32, r0 = blockIdx.y * 32;
    const int tx = threadIdx.x & 31, ty = threadIdx.x >> 5;
    #pragma unroll
    for (int dy = 0; dy < 32; dy += 8)
        tile[ty + dy][tx] = src[(long long)(r0 + ty + dy) * C + c0 + tx];
    __syncthreads();
    #pragma unroll
    for (int dy = 0; dy < 32; dy += 8)
        dst[(long long)(c0 + ty + dy) * R + r0 + tx] = __float2half_rn(tile[tx][ty + dy]);
}

// ---------------------------------------------------------------- LayerNorm
template<bool OUTH>
__global__ __launch_bounds__(256) void ln_k(
    const float* __restrict__ x, const float* __restrict__ g,
    const float* __restrict__ b, void* __restrict__ outv)
{
    __shared__ float sm0[8], sm1[8];
    const int row = blockIdx.x, tid = threadIdx.x;
    float4 v = ((const float4*)(x + (long long)row * Dd))[tid];
    float s  = v.x + v.y + v.z + v.w;
    float s2 = v.x * v.x + v.y * v.y + v.z * v.z + v.w * v.w;
    #pragma unroll
    for (int o = 16; o > 0; o >>= 1) {
        s  += __shfl_xor_sync(0xffffffffu, s,  o);
        s2 += __shfl_xor_sync(0xffffffffu, s2, o);
    }
    if ((tid & 31) == 0) { sm0[tid >> 5] = s; sm1[tid >> 5] = s2; }
    __syncthreads();
    if (tid < 32) {
        s  = (tid < 8) ? sm0[tid] : 0.f;
        s2 = (tid < 8) ? sm1[tid] : 0.f;
        #pragma unroll
        for (int o = 4; o > 0; o >>= 1) {
            s  += __shfl_xor_sync(0xffffffffu, s,  o);
            s2 += __shfl_xor_sync(0xffffffffu, s2, o);
        }
        if (tid == 0) { sm0[0] = s; sm1[0] = s2; }
    }
    __syncthreads();
    const float mean = sm0[0] * (1.f / Dd);
    const float var  = sm1[0] * (1.f / Dd) - mean * mean;
    const float rstd = rsqrtf(var + 1e-5f);
    float4 gg = ((const float4*)g)[tid];
    float4 bb = ((const float4*)b)[tid];
    float4 o;
    o.x = (v.x - mean) * rstd * gg.x + bb.x;
    o.y = (v.y - mean) * rstd * gg.y + bb.y;
    o.z = (v.z - mean) * rstd * gg.z + bb.z;
    o.w = (v.w - mean) * rstd * gg.w + bb.w;
    if (OUTH) {
        __half2* oh = (__half2*)((__half*)outv + (long long)row * Dd);
        oh[2 * tid]     = __floats2half2_rn(o.x, o.y);
        oh[2 * tid + 1] = __floats2half2_rn(o.z, o.w);
    } else {
        ((float4*)((float*)outv + (long long)row * Dd))[tid] = o;
    }
}

// ---------------------------------------------------------------- Softmax (half in/out, fp32 math)
__global__ __launch_bounds__(256) void softmax_k(__half* __restrict__ attn)
{
    __shared__ float sm[8];
    const int row = blockIdx.x;
    const int q   = row & (Ss - 1);
    __half* p = attn + (long long)row * Ss;
    const int tid = threadIdx.x;
    const int k0  = tid * 4;
    __half2 h0 = ((const __half2*)p)[2 * tid];
    __half2 h1 = ((const __half2*)p)[2 * tid + 1];
    float4 v = make_float4(__low2float(h0), __high2float(h0),
                           __low2float(h1), __high2float(h1));

    float m = -1e30f;
    if (k0 + 0 <= q) m = fmaxf(m, v.x);
    if (k0 + 1 <= q) m = fmaxf(m, v.y);
    if (k0 + 2 <= q) m = fmaxf(m, v.z);
    if (k0 + 3 <= q) m = fmaxf(m, v.w);
    #pragma unroll
    for (int o = 16; o > 0; o >>= 1) m = fmaxf(m, __shfl_xor_sync(0xffffffffu, m, o));
    if ((tid & 31) == 0) sm[tid >> 5] = m;
    __syncthreads();
    if (tid < 32) {
        float t = (tid < 8) ? sm[tid] : -1e30f;
        #pragma unroll
        for (int o = 4; o > 0; o >>= 1) t = fmaxf(t, __shfl_xor_sync(0xffffffffu, t, o));
        if (tid == 0) sm[0] = t;
    }
    __syncthreads();
    m = sm[0];
    __syncthreads();

    float4 e;
    e.x = (k0 + 0 <= q) ? __expf(v.x - m) : 0.f;
    e.y = (k0 + 1 <= q) ? __expf(v.y - m) : 0.f;
    e.z = (k0 + 2 <= q) ? __expf(v.z - m) : 0.f;
    e.w = (k0 + 3 <= q) ? __expf(v.w - m) : 0.f;
    float s = e.x + e.y + e.z + e.w;
    #pragma unroll
    for (int o = 16; o > 0; o >>= 1) s += __shfl_xor_sync(0xffffffffu, s, o);
    if ((tid & 31) == 0) sm[tid >> 5] = s;
    __syncthreads();
    if (tid < 32) {
        float t = (tid < 8) ? sm[tid] : 0.f;
        #pragma unroll
        for (int o = 4; o > 0; o >>= 1) t += __shfl_xor_sync(0xffffffffu, t, o);
        if (tid == 0) sm[0] = t;
    }
    __syncthreads();
    const float inv = 1.f / sm[0];
    ((__half2*)p)[2 * tid]     = __floats2half2_rn(e.x * inv, e.y * inv);
    ((__half2*)p)[2 * tid + 1] = __floats2half2_rn(e.z * inv, e.w * inv);
}

// ---------------------------------------------------------------- Column sums (half attn, fp32 acc)
__global__ __launch_bounds__(256) void colsum_part_k(
    const __half* __restrict__ attn, float* __restrict__ part)
{
    const int k  = blockIdx.x * 256 + threadIdx.x;
    const int b  = blockIdx.y;
    const int rs = blockIdx.z;
    const int RC = Hh * Ss / RSPLIT;
    const __half* base = attn + (long long)b * Hh * Ss * Ss
                              + (long long)rs * RC * Ss + k;
    float s = 0.f;
    #pragma unroll 8
    for (int r = 0; r < RC; r++) s += __half2float(base[(long long)r * Ss]);
    part[(rs * Bb + b) * Ss + k] = s;
}

__global__ __launch_bounds__(256) void colsum_fin_k(
    const float* __restrict__ part, float* __restrict__ amap)
{
    const int i = blockIdx.x * 256 + threadIdx.x;
    float s = 0.f;
    #pragma unroll
    for (int rs = 0; rs < RSPLIT; rs++) s += part[rs * Bb * Ss + i];
    amap[i] += s;
}

// ---------------------------------------------------------------- misc
__global__ __launch_bounds__(256) void init_x_snap_k(
    const float4* __restrict__ token, float4* __restrict__ x,
    float4* __restrict__ st)
{
    const int i = blockIdx.x * 256 + threadIdx.x;
    float4 v = token[i];
    x[i] = v;
    st[((long long)(i >> 8) * DEPTH + 0) * 256 + (i & 255)] = v;
}

__global__ void zero_k(float* p, int n)
{
    int i = blockIdx.x * 256 + threadIdx.x;
    if (i < n) p[i] = 0.f;
}

// ---------------------------------------------------------------- launcher
extern "C" void kernel_launch(void* const* d_in, const int* in_sizes, int n_in,
                              void* d_out, int out_size)
{
    const float* token = (const float*)d_in[0];
    const float* Wq    = (const float*)d_in[1];
    const float* Wkv   = (const float*)d_in[2];
    const float* Wo    = (const float*)d_in[3];
    const float* b_o   = (const float*)d_in[4];
    const float* g1    = (const float*)d_in[5];
    const float* b1    = (const float*)d_in[6];
    const float* g3    = (const float*)d_in[7];
    const float* b3    = (const float*)d_in[8];
    const float* W1    = (const float*)d_in[9];
    const float* W2    = (const float*)d_in[10];
    const float* gout  = (const float*)d_in[11];
    const float* bout  = (const float*)d_in[12];
    float* out = (float*)d_out;

    float *x, *red, *part;
    __half *xn, *qkv, *wqkvT, *woT, *w1T, *w2T, *attn, *y, *ff;
    cudaGetSymbolAddress((void**)&x,     g_x);
    cudaGetSymbolAddress((void**)&xn,    g_xn);
    cudaGetSymbolAddress((void**)&qkv,   g_qkv);
    cudaGetSymbolAddress((void**)&wqkvT, g_wqkvT);
    cudaGetSymbolAddress((void**)&woT,   g_woT);
    cudaGetSymbolAddress((void**)&w1T,   g_w1T);
    cudaGetSymbolAddress((void**)&w2T,   g_w2T);
    cudaGetSymbolAddress((void**)&attn,  g_attn);
    cudaGetSymbolAddress((void**)&y,     g_y);
    cudaGetSymbolAddress((void**)&ff,    g_ff);
    cudaGetSymbolAddress((void**)&red,   g_red);
    cudaGetSymbolAddress((void**)&part,  g_part);

    cudaFuncSetAttribute(gemm_h<0, true,  true >, cudaFuncAttributeMaxDynamicSharedMemorySize, GEMM_SMEM);
    cudaFuncSetAttribute(gemm_h<0, true,  false>, cudaFuncAttributeMaxDynamicSharedMemorySize, GEMM_SMEM);
    cudaFuncSetAttribute(gemm_h<0, false, true >, cudaFuncAttributeMaxDynamicSharedMemorySize, GEMM_SMEM);
    cudaFuncSetAttribute(gemm_h<2, true,  true >, cudaFuncAttributeMaxDynamicSharedMemorySize, GEMM_SMEM);

    float* out_state = out + (size_t)BS * Dd;
    float* amap      = out_state + (size_t)BS * DEPTH * Dd;

    init_x_snap_k<<<BS * Dd / 4 / 256, 256>>>((const float4*)token, (float4*)x,
                                              (float4*)out_state);
    zero_k<<<(BS + 255) / 256, 256>>>(amap, BS);

    const int D3 = 3 * Dd;
    transpose_cvt_k<<<dim3(Dd / 32, Dd / 32, DEPTH), 256>>>(
        Wq, wqkvT, Dd, Dd, (long long)Dd * Dd, (long long)D3 * Dd);
    transpose_cvt_k<<<dim3(2 * Dd / 32, Dd / 32, DEPTH), 256>>>(
        Wkv, wqkvT + (size_t)Dd * Dd, Dd, 2 * Dd,
        (long long)Dd * 2 * Dd, (long long)D3 * Dd);
    transpose_cvt_k<<<dim3(Dd / 32, Dd / 32, DEPTH), 256>>>(
        Wo, woT, Dd, Dd, (long long)Dd * Dd, (long long)Dd * Dd);
    transpose_cvt_k<<<dim3(FF / 32, Dd / 32, DEPTH), 256>>>(
        W1, w1T, Dd, FF, (long long)Dd * FF, (long long)Dd * FF);
    transpose_cvt_k<<<dim3(Dd / 32, FF / 32, DEPTH), 256>>>(
        W2, w2T, FF, Dd, (long long)FF * Dd, (long long)FF * Dd);

    const float scale = rsqrtf((float)HD);
    const int NRED = BS * Dd / 4 / 256;

    for (int l = 0; l < DEPTH; l++) {
        // LN1 -> half xn
        ln_k<true><<<BS, 256>>>(x, g1 + l * Dd, b1 + l * Dd, xn);
        // QKV = xn @ [Wq|Wkv]^T  (TRANSB, half out)
        gemm_h<0, true, true><<<dim3(D3 / BN, BS / BM, 1), 128, GEMM_SMEM>>>(
            xn, wqkvT + (size_t)l * D3 * Dd, qkv,
            Dd, Dd, Dd, D3, 0, 0, 0, 0, 0, 0, 1, 1.f, 0);
        // scores = scale * Q @ K^T (TRANSB, half out, causal tile-skip)
        gemm_h<0, true, true><<<dim3(Ss / BN, Ss / BM, Bb * Hh), 128, GEMM_SMEM>>>(
            qkv, qkv + Dd, attn,
            HD, D3, D3, Ss,
            (long long)Ss * D3, HD,
            (long long)Ss * D3, HD,
            (long long)Hh * Ss * Ss, (long long)Ss * Ss,
            Hh, scale, 1);
        // softmax rows
        softmax_k<<<Bb * Hh * Ss, 256>>>(attn);
        // attention-map column sums
        colsum_part_k<<<dim3(Ss / 256, Bb, RSPLIT), 256>>>(attn, part);
        colsum_fin_k<<<Bb * Ss / 256, 256>>>(part, amap);
        // y = attn @ V (non-trans B, K-trim, half out)
        gemm_h<0, false, true><<<dim3(HD / BN, Ss / BM, Bb * Hh), 128, GEMM_SMEM>>>(
            attn, qkv + 2 * Dd, y,
            Ss, Ss, D3, Dd,
            (long long)Hh * Ss * Ss, (long long)Ss * Ss,
            (long long)Ss * D3, HD,
            (long long)Ss * Dd, HD,
            Hh, 1.f, 2);
        // x += y @ Wo + b_o  (TRANSB, split-K=2, fp32 partials)
        gemm_h<0, true, false><<<dim3(Dd / BN, BS / BM, 2), 128, GEMM_SMEM>>>(
            y, woT + (size_t)l * Dd * Dd, red,
            Dd / 2, Dd, Dd, Dd,
            0, Dd / 2, 0, Dd / 2,
            0, (long long)BS * Dd,
            2, 1.f, 0);
        reduce_add_k<2, true, false><<<NRED, 256>>>(
            (const float4*)red, (float4*)x, b_o + l * Dd, nullptr, 0);
        // LN2 -> half xn
        ln_k<true><<<BS, 256>>>(x, g3 + l * Dd, b3 + l * Dd, xn);
        // ff = gelu(xn @ W1^T)  (TRANSB, half out)
        gemm_h<2, true, true><<<dim3(FF / BN, BS / BM, 1), 128, GEMM_SMEM>>>(
            xn, w1T + (size_t)l * FF * Dd, ff,
            Dd, Dd, Dd, FF, 0, 0, 0, 0, 0, 0, 1, 1.f, 0);
        // x += ff @ W2^T  (TRANSB, split-K=4, fp32 partials)
        gemm_h<0, true, false><<<dim3(Dd / BN, BS / BM, 4), 128, GEMM_SMEM>>>(
            ff, w2T + (size_t)l * Dd * FF, red,
            FF / 4, FF, FF, Dd,
            0, FF / 4, 0, FF / 4,
            0, (long long)BS * Dd,
            4, 1.f, 0);
        if (l < DEPTH - 1)
            reduce_add_k<4, false, true><<<NRED, 256>>>(
                (const float4*)red, (float4*)x, nullptr, (float4*)out_state, l + 1);
        else
            reduce_add_k<4, false, false><<<NRED, 256>>>(
                (const float4*)red, (float4*)x, nullptr, nullptr, 0);
    }
    // final LN -> x_out (fp32)
    ln_k<false><<<BS, 256>>>(x, gout, bout, out);
}